// round 3
// baseline (speedup 1.0000x reference)
#include <cuda_runtime.h>
#include <cuda_bf16.h>
#include <cstdint>
#include <cstddef>

// ---------------------------------------------------------------------------
// Problem constants
// ---------------------------------------------------------------------------
#define HID     1536
#define NH      12
#define HD      128
#define MLP     6144
#define LX      4352          // 256 + 4096
#define NC      20
#define L2V     4116          // 20 + 4096 (valid rows, block 2)
#define L2P     4224          // padded to multiple of 128
#define W1ROWS  10752         // 3*HID + MLP
#define CATW    7680          // HID + MLP
#define SOFT_SCALE 0.08838834764831845f   // 1/sqrt(128)

typedef unsigned long long u64;

// ---------------------------------------------------------------------------
// Scratch (device globals; zero-initialized at module load; rows we never
// write stay zero on every call => deterministic)
// ---------------------------------------------------------------------------
__device__ float g_m[3 * HID];                       // shift|scale|gate
__device__ float g_xm[(size_t)LX * HID];
__device__ float g_h[(size_t)LX * W1ROWS];
__device__ float g_h2kv[(size_t)L2P * 3072];
__device__ float g_h2f[(size_t)128 * W1ROWS];
__device__ float g_q[(size_t)NH * LX * HD];
__device__ float g_k[(size_t)NH * LX * HD];
__device__ float g_v[(size_t)NH * LX * HD];
__device__ float g_q2[(size_t)NH * 128 * HD];
__device__ float g_k2[(size_t)NH * L2P * HD];
__device__ float g_v2[(size_t)NH * L2P * HD];
__device__ float g_S[(size_t)NH * LX * LX];          // ~909 MB
__device__ float g_S2[(size_t)NH * 128 * L2P];
__device__ float g_O[(size_t)NH * LX * HD];
__device__ float g_O2[(size_t)NH * 128 * HD];
__device__ float g_cat[(size_t)LX * CATW];
__device__ float g_cat2[(size_t)128 * CATW];

// ---------------------------------------------------------------------------
// Packed f32x2 helpers (Blackwell FFMA2: 2x fp32 throughput, exact fp32)
// ---------------------------------------------------------------------------
__device__ __forceinline__ u64 pack2(float lo, float hi) {
    u64 r;
    asm("mov.b64 %0, {%1, %2};" : "=l"(r) : "f"(lo), "f"(hi));
    return r;
}
__device__ __forceinline__ void unpack2(u64 p, float& lo, float& hi) {
    asm("mov.b64 {%0, %1}, %2;" : "=f"(lo), "=f"(hi) : "l"(p));
}
__device__ __forceinline__ void fma2(u64& d, u64 a, u64 b) {
    asm("fma.rn.f32x2 %0, %1, %2, %0;" : "+l"(d) : "l"(a), "l"(b));
}

// ---------------------------------------------------------------------------
// Generic tiled SGEMM: C[M,N] = A(MxK) * op(B) (+bias) (+residual epilogue)
//   BMODE 0 (NT): B is (N x K) row-major,   C[m,n] = sum_k A[m,k]*B[n,k]
//   BMODE 1 (NN): B is (K x N) row-major,   C[m,n] = sum_k A[m,k]*B[k,n]
//   EPI 0: C = acc (+bias)      EPI 1: C = res + gate * (acc + bias)
// Requirements: K % 16 == 0; all leading dims % 4 == 0 (true for every call).
// Batched via blockIdx.z with element strides sA/sB/sC.
// ---------------------------------------------------------------------------
#define BM 128
#define BN 128

template <int BMODE, int EPI>
__global__ __launch_bounds__(256)
void gemm_kernel(const float* __restrict__ A, const float* __restrict__ B,
                 float* __restrict__ C,
                 int M, int N, int K, int lda, int ldb, int ldc,
                 size_t sA, size_t sB, size_t sC,
                 const float* __restrict__ bias,
                 const float* __restrict__ res, int ldres,
                 const float* __restrict__ gate)
{
    A += (size_t)blockIdx.z * sA;
    B += (size_t)blockIdx.z * sB;
    C += (size_t)blockIdx.z * sC;
    const int bm = blockIdx.y * BM;
    const int bn = blockIdx.x * BN;

    __shared__ float As[16][BM + 4];
    __shared__ float Bs[16][BN + 4];

    const int tid = threadIdx.x;          // 0..255
    const int tx = tid & 15;
    const int ty = tid >> 4;

    u64 acc[8][4];
#pragma unroll
    for (int i = 0; i < 8; i++)
#pragma unroll
        for (int j = 0; j < 4; j++) acc[i][j] = 0ull;

    const int aRow  = tid >> 2;           // 0..63
    const int aK    = (tid & 3) * 4;      // 0,4,8,12
    const int bkRow = tid >> 5;           // 0..7   (NN)
    const int bnCol = (tid & 31) * 4;     // 0..124 (NN)

    for (int kt = 0; kt < K; kt += 16) {
        // ---- load A tile (128 x 16), transposed into As[k][m]
#pragma unroll
        for (int r = 0; r < 2; r++) {
            int row = aRow + 64 * r;
            float4 val = make_float4(0.f, 0.f, 0.f, 0.f);
            if (bm + row < M)
                val = *(const float4*)(A + (size_t)(bm + row) * lda + kt + aK);
            As[aK + 0][row] = val.x;
            As[aK + 1][row] = val.y;
            As[aK + 2][row] = val.z;
            As[aK + 3][row] = val.w;
        }
        // ---- load B tile
        if (BMODE == 0) {
#pragma unroll
            for (int r = 0; r < 2; r++) {
                int n = aRow + 64 * r;
                float4 val = make_float4(0.f, 0.f, 0.f, 0.f);
                if (bn + n < N)
                    val = *(const float4*)(B + (size_t)(bn + n) * ldb + kt + aK);
                Bs[aK + 0][n] = val.x;
                Bs[aK + 1][n] = val.y;
                Bs[aK + 2][n] = val.z;
                Bs[aK + 3][n] = val.w;
            }
        } else {
#pragma unroll
            for (int r = 0; r < 2; r++) {
                int kr = bkRow + 8 * r;
                float4 val = make_float4(0.f, 0.f, 0.f, 0.f);
                if (bn + bnCol < N)
                    val = *(const float4*)(B + (size_t)(kt + kr) * ldb + bn + bnCol);
                *(float4*)&Bs[kr][bnCol] = val;
            }
        }
        __syncthreads();

        // ---- 8x8 microtile via FFMA2 (accumulate 2 N-columns per op)
#pragma unroll
        for (int kk = 0; kk < 16; kk++) {
            float4 a0 = *(const float4*)&As[kk][ty * 8];
            float4 a1 = *(const float4*)&As[kk][ty * 8 + 4];
            u64 bp0 = *(const u64*)&Bs[kk][tx * 8 + 0];
            u64 bp1 = *(const u64*)&Bs[kk][tx * 8 + 2];
            u64 bp2 = *(const u64*)&Bs[kk][tx * 8 + 4];
            u64 bp3 = *(const u64*)&Bs[kk][tx * 8 + 6];
            float av[8] = {a0.x, a0.y, a0.z, a0.w, a1.x, a1.y, a1.z, a1.w};
#pragma unroll
            for (int i = 0; i < 8; i++) {
                u64 ap = pack2(av[i], av[i]);
                fma2(acc[i][0], ap, bp0);
                fma2(acc[i][1], ap, bp1);
                fma2(acc[i][2], ap, bp2);
                fma2(acc[i][3], ap, bp3);
            }
        }
        __syncthreads();
    }

    // ---- epilogue
#pragma unroll
    for (int i = 0; i < 8; i++) {
        int row = bm + ty * 8 + i;
        if (row < M) {
            float* crow = C + (size_t)row * ldc;
            const float* rrow = (EPI == 1) ? (res + (size_t)row * ldres) : nullptr;
#pragma unroll
            for (int j = 0; j < 4; j++) {
                float lo, hi;
                unpack2(acc[i][j], lo, hi);
                int c0 = bn + tx * 8 + 2 * j;
                if (c0 < N) {
                    float vv = lo + (bias ? bias[c0] : 0.f);
                    if (EPI == 1) vv = rrow[c0] + gate[c0] * vv;
                    crow[c0] = vv;
                }
                int c1 = c0 + 1;
                if (c1 < N) {
                    float vv = hi + (bias ? bias[c1] : 0.f);
                    if (EPI == 1) vv = rrow[c1] + gate[c1] * vv;
                    crow[c1] = vv;
                }
            }
        }
    }
}

// ---------------------------------------------------------------------------
// m = silu(vec) @ mod_w.T + mod_b   (one block per output)
// ---------------------------------------------------------------------------
__global__ void mod_kernel(const float* __restrict__ vec,
                           const float* __restrict__ mw,
                           const float* __restrict__ mb,
                           float* __restrict__ m)
{
    int o = blockIdx.x, t = threadIdx.x;
    float s = 0.f;
    for (int k = t; k < HID; k += 256) {
        float v = vec[k];
        s += (v / (1.f + expf(-v))) * mw[(size_t)o * HID + k];
    }
    __shared__ float red[256];
    red[t] = s; __syncthreads();
    for (int st = 128; st > 0; st >>= 1) {
        if (t < st) red[t] += red[t + st];
        __syncthreads();
    }
    if (t == 0) m[o] = red[0] + mb[o];
}

// ---------------------------------------------------------------------------
// xm = (1 + scale) * LayerNorm(in) + shift   (one block per token)
// ---------------------------------------------------------------------------
__global__ void ln_mod_kernel(const float* __restrict__ in,
                              float* __restrict__ out,
                              const float* __restrict__ m)
{
    int row = blockIdx.x, t = threadIdx.x;
    const float* x = in + (size_t)row * HID;
    __shared__ float buf[HID];
    __shared__ float red[256];

    float s = 0.f;
    for (int c = t; c < HID; c += 256) { float v = x[c]; buf[c] = v; s += v; }
    red[t] = s; __syncthreads();
    for (int st = 128; st > 0; st >>= 1) { if (t < st) red[t] += red[t + st]; __syncthreads(); }
    float mu = red[0] * (1.f / HID);
    __syncthreads();

    float ss = 0.f;
    for (int c = t; c < HID; c += 256) { float d = buf[c] - mu; ss += d * d; }
    red[t] = ss; __syncthreads();
    for (int st = 128; st > 0; st >>= 1) { if (t < st) red[t] += red[t + st]; __syncthreads(); }
    float inv = rsqrtf(red[0] * (1.f / HID) + 1e-6f);

    float* o = out + (size_t)row * HID;
    for (int c = t; c < HID; c += 256)
        o[c] = (1.f + m[HID + c]) * ((buf[c] - mu) * inv) + m[c];
}

// ---------------------------------------------------------------------------
// Per-(token, head): optional rmsnorm(scale) + optional RoPE, write to
// head-major dst[hd][l][d]. pe layout: [L][64][2][2].
// ---------------------------------------------------------------------------
__global__ void rmsrope_kernel(const float* __restrict__ src, int ldh,
                               const float* __restrict__ pe,
                               const float* __restrict__ scale, int dorope,
                               float* __restrict__ dst, int dstL)
{
    int l = blockIdx.x, hd = blockIdx.y, d = threadIdx.x;   // 128 threads
    float v = src[(size_t)l * ldh + hd * HD + d];
    __shared__ float sv[HD];
    __shared__ float wred[4];

    if (scale) {
        float ss = v * v;
#pragma unroll
        for (int o = 16; o > 0; o >>= 1) ss += __shfl_xor_sync(0xffffffffu, ss, o);
        if ((d & 31) == 0) wred[d >> 5] = ss;
        __syncthreads();
        float tot = wred[0] + wred[1] + wred[2] + wred[3];
        v = v * rsqrtf(tot * (1.f / HD) + 1e-6f) * scale[d];
        __syncthreads();
    }
    float outv;
    if (dorope) {
        sv[d] = v; __syncthreads();
        int i = d >> 1, j = d & 1;
        const float* pp = pe + (size_t)l * 256 + i * 4 + j * 2;
        outv = pp[0] * sv[2 * i] + pp[1] * sv[2 * i + 1];
    } else {
        outv = v;
    }
    dst[((size_t)hd * dstL + l) * HD + d] = outv;
}

// ---------------------------------------------------------------------------
// Row softmax (with pre-scale), smem-cached; zeroes padded cols >= Nvalid.
// S row pointer = S + (head*rowStride + row) * Npad
// ---------------------------------------------------------------------------
__global__ void softmax_kernel(float* __restrict__ S, int rowStride,
                               int Npad, int Nvalid, float scale)
{
    int row = blockIdx.x, head = blockIdx.y, t = threadIdx.x;
    float* p = S + ((size_t)head * rowStride + row) * Npad;
    __shared__ float srow[LX];
    __shared__ float red[256];

    float mx = -1e30f;
    for (int j = t; j < Nvalid; j += 256) {
        float v = p[j] * scale;
        srow[j] = v;
        mx = fmaxf(mx, v);
    }
    red[t] = mx; __syncthreads();
    for (int st = 128; st > 0; st >>= 1) { if (t < st) red[t] = fmaxf(red[t], red[t + st]); __syncthreads(); }
    mx = red[0];
    __syncthreads();

    float sum = 0.f;
    for (int j = t; j < Nvalid; j += 256) {
        float e = __expf(srow[j] - mx);
        srow[j] = e;
        sum += e;
    }
    red[t] = sum; __syncthreads();
    for (int st = 128; st > 0; st >>= 1) { if (t < st) red[t] += red[t + st]; __syncthreads(); }
    float inv = 1.f / red[0];

    for (int j = t; j < Nvalid; j += 256) p[j] = srow[j] * inv;
    for (int j = Nvalid + t; j < Npad; j += 256) p[j] = 0.f;
}

// ---------------------------------------------------------------------------
// cat[l][0:1536] = attn (gather from head-major O), cat[l][1536:] = gelu(mlp)
// ---------------------------------------------------------------------------
__global__ void cat_kernel(const float* __restrict__ O, int OL,
                           const float* __restrict__ mlp, int ldm,
                           float* __restrict__ cat)
{
    int l = blockIdx.y;
    int c = blockIdx.x * 256 + threadIdx.x;   // < 7680
    float v;
    if (c < HID) {
        int hd = c >> 7, d = c & 127;
        v = O[((size_t)hd * OL + l) * HD + d];
    } else {
        float xg = mlp[(size_t)l * ldm + (c - HID)];
        float u = 0.7978845608028654f * (xg + 0.044715f * xg * xg * xg);
        v = 0.5f * xg * (1.f + tanhf(u));
    }
    cat[(size_t)l * CATW + c] = v;
}

// ---------------------------------------------------------------------------
// kernel_launch
// ---------------------------------------------------------------------------
extern "C" void kernel_launch(void* const* d_in, const int* in_sizes, int n_in,
                              void* d_out, int out_size)
{
    (void)in_sizes; (void)n_in; (void)out_size;
    const float* x   = (const float*)d_in[0];
    const float* cps = (const float*)d_in[1];
    const float* vec = (const float*)d_in[2];
    const float* pe  = (const float*)d_in[3];
    const float* cpe = (const float*)d_in[4];
    const float* w1  = (const float*)d_in[5];
    const float* b1  = (const float*)d_in[6];
    const float* w2  = (const float*)d_in[7];
    const float* b2  = (const float*)d_in[8];
    const float* qs  = (const float*)d_in[9];
    const float* ks  = (const float*)d_in[10];
    const float* mw  = (const float*)d_in[11];
    const float* mb  = (const float*)d_in[12];
    float* out = (float*)d_out;

    float *m, *xm, *h, *h2kv, *h2f, *q, *k, *v, *q2, *k2, *v2, *S, *S2, *O, *O2, *cat, *cat2;
    cudaGetSymbolAddress((void**)&m,    g_m);
    cudaGetSymbolAddress((void**)&xm,   g_xm);
    cudaGetSymbolAddress((void**)&h,    g_h);
    cudaGetSymbolAddress((void**)&h2kv, g_h2kv);
    cudaGetSymbolAddress((void**)&h2f,  g_h2f);
    cudaGetSymbolAddress((void**)&q,    g_q);
    cudaGetSymbolAddress((void**)&k,    g_k);
    cudaGetSymbolAddress((void**)&v,    g_v);
    cudaGetSymbolAddress((void**)&q2,   g_q2);
    cudaGetSymbolAddress((void**)&k2,   g_k2);
    cudaGetSymbolAddress((void**)&v2,   g_v2);
    cudaGetSymbolAddress((void**)&S,    g_S);
    cudaGetSymbolAddress((void**)&S2,   g_S2);
    cudaGetSymbolAddress((void**)&O,    g_O);
    cudaGetSymbolAddress((void**)&O2,   g_O2);
    cudaGetSymbolAddress((void**)&cat,  g_cat);
    cudaGetSymbolAddress((void**)&cat2, g_cat2);

    // ---- modulation vector: m = silu(vec) @ mod_w.T + mod_b
    mod_kernel<<<3 * HID, 256>>>(vec, mw, mb, m);

    // ================= Block 1 (L = 4352) =================
    ln_mod_kernel<<<LX, 256>>>(x, xm, m);

    // h = xm @ w1.T + b1   (4352 x 10752, K=1536)
    gemm_kernel<0, 0><<<dim3(W1ROWS / BN, LX / BM, 1), 256>>>(
        xm, w1, h, LX, W1ROWS, HID, HID, HID, W1ROWS,
        0, 0, 0, b1, nullptr, 0, nullptr);

    dim3 gqk(LX, NH);
    rmsrope_kernel<<<gqk, HD>>>(h + 0,      W1ROWS, pe, qs,      1, q, LX);
    rmsrope_kernel<<<gqk, HD>>>(h + HID,    W1ROWS, pe, ks,      1, k, LX);
    rmsrope_kernel<<<gqk, HD>>>(h + 2*HID,  W1ROWS, pe, nullptr, 0, v, LX);

    // S = q @ k^T  (batched over heads)
    gemm_kernel<0, 0><<<dim3(LX / BN, LX / BM, NH), 256>>>(
        q, k, S, LX, LX, HD, HD, HD, LX,
        (size_t)LX * HD, (size_t)LX * HD, (size_t)LX * LX,
        nullptr, nullptr, 0, nullptr);

    softmax_kernel<<<dim3(LX, NH), 256>>>(S, LX, LX, LX, SOFT_SCALE);

    // O = P @ V
    gemm_kernel<1, 0><<<dim3(1, LX / BM, NH), 256>>>(
        S, v, O, LX, HD, LX, LX, HD, HD,
        (size_t)LX * LX, (size_t)LX * HD, (size_t)LX * HD,
        nullptr, nullptr, 0, nullptr);

    cat_kernel<<<dim3(CATW / 256, LX), 256>>>(O, LX, h + 3 * HID, W1ROWS, cat);

    // out_x = x + gate * (cat @ w2.T + b2)
    gemm_kernel<0, 1><<<dim3(HID / BN, LX / BM, 1), 256>>>(
        cat, w2, out, LX, HID, CATW, CATW, CATW, HID,
        0, 0, 0, b2, x, HID, m + 2 * HID);

    // ================= Block 2 (L = 4116, only 20 output rows kept) =========
    ln_mod_kernel<<<NC, 256>>>(cps, xm, m);
    ln_mod_kernel<<<LX - NC - 256 + 256, 256>>>(x + (size_t)256 * HID,
                                                xm + (size_t)NC * HID, m);
    // (grid = 4096 image tokens)

    // k,v for all 4116 rows (cols 1536..4607 of w1 only)
    gemm_kernel<0, 0><<<dim3(3072 / BN, L2P / BM, 1), 256>>>(
        xm, w1 + (size_t)HID * HID, h2kv, L2V, 3072, HID, HID, HID, 3072,
        0, 0, 0, b1 + HID, nullptr, 0, nullptr);

    // full h (q + mlp) for the 20 concept rows only
    gemm_kernel<0, 0><<<dim3(W1ROWS / BN, 1, 1), 256>>>(
        xm, w1, h2f, NC, W1ROWS, HID, HID, HID, W1ROWS,
        0, 0, 0, b1, nullptr, 0, nullptr);

    dim3 gk2(L2V, NH);
    rmsrope_kernel<<<gk2, HD>>>(h2kv + 0,   3072, cpe, ks,      1, k2, L2P);
    rmsrope_kernel<<<gk2, HD>>>(h2kv + HID, 3072, cpe, nullptr, 0, v2, L2P);
    rmsrope_kernel<<<dim3(NC, NH), HD>>>(h2f + 0, W1ROWS, cpe, qs, 1, q2, 128);

    gemm_kernel<0, 0><<<dim3(L2P / BN, 1, NH), 256>>>(
        q2, k2, S2, NC, L2P, HD, HD, HD, L2P,
        (size_t)128 * HD, (size_t)L2P * HD, (size_t)128 * L2P,
        nullptr, nullptr, 0, nullptr);

    softmax_kernel<<<dim3(NC, NH), 256>>>(S2, 128, L2P, L2V, SOFT_SCALE);

    gemm_kernel<1, 0><<<dim3(1, 1, NH), 256>>>(
        S2, v2, O2, NC, HD, L2P, L2P, HD, HD,
        (size_t)128 * L2P, (size_t)L2P * HD, (size_t)128 * HD,
        nullptr, nullptr, 0, nullptr);

    cat_kernel<<<dim3(CATW / 256, NC), 256>>>(O2, 128, h2f + 3 * HID, W1ROWS, cat2);

    // concepts_out = concepts + gate * (cat2 @ w2.T + b2)
    gemm_kernel<0, 1><<<dim3(HID / BN, 1, 1), 256>>>(
        cat2, w2, out + (size_t)LX * HID, NC, HID, CATW, CATW, CATW, HID,
        0, 0, 0, b2, cps, HID, m + 2 * HID);
}

// round 5
// speedup vs baseline: 3.8632x; 3.8632x over previous
#include <cuda_runtime.h>
#include <cuda_bf16.h>
#include <cstdint>
#include <cstddef>

// ---------------------------------------------------------------------------
// Problem constants
// ---------------------------------------------------------------------------
#define HID     1536
#define NH      12
#define HD      128
#define MLP     6144
#define LX      4352          // 256 + 4096
#define NC      20
#define L2V     4116          // 20 + 4096 (valid rows, block 2)
#define L2P     4352          // padded to multiple of 256
#define W1ROWS  10752         // 3*HID + MLP
#define CATW    7680          // HID + MLP
#define SOFT_SCALE 0.08838834764831845f   // 1/sqrt(128)

typedef unsigned int u32;
typedef unsigned long long u64;

// tcgen05 exists only in the 'a' (arch-accelerated) targets. The harness also
// compiles a plain compute_103 pass; these instructions must vanish there.
#if defined(__CUDA_ARCH_FEAT_SM103_ALL) || defined(__CUDA_ARCH_FEAT_SM100_ALL) || defined(__CUDA_ARCH_FEAT_SM101_ALL)
#define HAS_TCGEN05 1
#else
#define HAS_TCGEN05 0
#endif

// ---------------------------------------------------------------------------
// Scratch (device globals; zero-initialized; rows never written stay zero)
// ---------------------------------------------------------------------------
__device__ __align__(256) float g_m[3 * HID];
__device__ __align__(256) float g_xm[(size_t)LX * HID];
__device__ __align__(256) float g_h[(size_t)LX * W1ROWS];
__device__ __align__(256) float g_h2kv[(size_t)L2P * 3072];
__device__ __align__(256) float g_h2f[(size_t)128 * W1ROWS];
__device__ __align__(256) float g_q[(size_t)NH * LX * HD];
__device__ __align__(256) float g_k[(size_t)NH * LX * HD];
__device__ __align__(256) float g_v[(size_t)NH * HD * LX];      // vT: [h][d][l]
__device__ __align__(256) float g_q2[(size_t)NH * 128 * HD];
__device__ __align__(256) float g_k2[(size_t)NH * L2P * HD];
__device__ __align__(256) float g_v2[(size_t)NH * HD * L2P];    // vT
__device__ __align__(256) float g_S[(size_t)NH * LX * LX];      // ~909 MB
__device__ __align__(256) float g_S2[(size_t)NH * 128 * L2P];
__device__ __align__(256) float g_O[(size_t)NH * LX * HD];
__device__ __align__(256) float g_O2[(size_t)NH * 128 * HD];
__device__ __align__(256) float g_cat[(size_t)LX * CATW];
__device__ __align__(256) float g_cat2[(size_t)128 * CATW];

// ---------------------------------------------------------------------------
// PTX helpers
// ---------------------------------------------------------------------------
__device__ __forceinline__ u32 s2u(const void* p) {
    return (u32)__cvta_generic_to_shared(p);
}
__device__ __forceinline__ u32 swz(u32 o) { return o ^ ((o >> 3) & 0x70); }

__device__ __forceinline__ void cp16(u32 dst, const void* src) {
    asm volatile("cp.async.cg.shared.global [%0], [%1], 16;" :: "r"(dst), "l"(src));
}
__device__ __forceinline__ void cp_commit() {
    asm volatile("cp.async.commit_group;" ::: "memory");
}
template <int N> __device__ __forceinline__ void cp_wait() {
    asm volatile("cp.async.wait_group %0;" :: "n"(N) : "memory");
}
__device__ __forceinline__ bool elect1() {
    u32 p;
    asm volatile("{\n\t.reg .pred p;\n\telect.sync _|p, 0xFFFFFFFF;\n\tselp.b32 %0,1,0,p;\n\t}"
                 : "=r"(p));
    return p != 0;
}
// SW128 K-major descriptor: layout=SW128, version=1, SBO=64 (1024B), LBO=1 (16B)
__device__ __forceinline__ u64 sdesc(u32 addr) {
    return 0x4000404000010000ull | (u64)((addr >> 4) & 0x3FFF);
}
__device__ __forceinline__ void mbar_init(u32 a) {
    u32 one = 1;
    asm volatile("mbarrier.init.shared.b64 [%0], %1;" :: "r"(a), "r"(one) : "memory");
}
__device__ __forceinline__ void mbar_wait(u32 a, u32 parity) {
    asm volatile(
        "{\n\t.reg .pred P;\n"
        "LW_%=:\n\t"
        "mbarrier.try_wait.parity.acquire.cta.shared::cta.b64 P, [%0], %1, 0x989680;\n\t"
        "@P bra LD_%=;\n\t"
        "bra LW_%=;\n"
        "LD_%=:\n\t}"
        :: "r"(a), "r"(parity) : "memory");
}
__device__ __forceinline__ void fence_async_shared() {
    asm volatile("fence.proxy.async.shared::cta;" ::: "memory");
}

// ---- tcgen05 family (guarded: only real on sm_103a-class targets) ---------
__device__ __forceinline__ void tc_commit(u32 mbar) {
#if HAS_TCGEN05
    asm volatile(
        "tcgen05.commit.cta_group::1.mbarrier::arrive::one.shared::cluster.b64 [%0];"
        :: "r"(mbar) : "memory");
#else
    (void)mbar;
#endif
}
__device__ __forceinline__ void mma_tf32(u32 d, u64 ad, u64 bd, u32 idesc, u32 en) {
#if HAS_TCGEN05
    asm volatile(
        "{\n\t.reg .pred p;\n\tsetp.ne.u32 p, %4, 0;\n\t"
        "tcgen05.mma.cta_group::1.kind::tf32 [%0], %1, %2, %3, {%5,%5,%5,%5}, p;\n\t}"
        :: "r"(d), "l"(ad), "l"(bd), "r"(idesc), "r"(en), "r"(0u) : "memory");
#else
    (void)d; (void)ad; (void)bd; (void)idesc; (void)en;
#endif
}
__device__ __forceinline__ void tc_fence_after() {
#if HAS_TCGEN05
    asm volatile("tcgen05.fence::after_thread_sync;" ::: "memory");
#endif
}
__device__ __forceinline__ void tmem_alloc(u32 dst_smem, u32 ncols) {
#if HAS_TCGEN05
    asm volatile("tcgen05.alloc.cta_group::1.sync.aligned.shared::cta.b32 [%0], %1;"
                 :: "r"(dst_smem), "r"(ncols) : "memory");
#else
    (void)dst_smem; (void)ncols;
#endif
}
__device__ __forceinline__ void tmem_relinquish() {
#if HAS_TCGEN05
    asm volatile("tcgen05.relinquish_alloc_permit.cta_group::1.sync.aligned;");
#endif
}
__device__ __forceinline__ void tmem_dealloc(u32 tmem, u32 ncols) {
#if HAS_TCGEN05
    asm volatile("tcgen05.dealloc.cta_group::1.sync.aligned.b32 %0, %1;" :: "r"(tmem), "r"(ncols));
#else
    (void)tmem; (void)ncols;
#endif
}
__device__ __forceinline__ void tmem_wait_ld() {
#if HAS_TCGEN05
    asm volatile("tcgen05.wait::ld.sync.aligned;" ::: "memory");
#endif
}
__device__ __forceinline__ void ldtm32(u32* r, u32 a) {
#if HAS_TCGEN05
    asm volatile(
        "tcgen05.ld.sync.aligned.32x32b.x32.b32 "
        "{%0, %1, %2, %3, %4, %5, %6, %7, "
        " %8, %9, %10, %11, %12, %13, %14, %15, "
        " %16, %17, %18, %19, %20, %21, %22, %23, "
        " %24, %25, %26, %27, %28, %29, %30, %31}, [%32];"
        : "=r"(r[0]),  "=r"(r[1]),  "=r"(r[2]),  "=r"(r[3]),
          "=r"(r[4]),  "=r"(r[5]),  "=r"(r[6]),  "=r"(r[7]),
          "=r"(r[8]),  "=r"(r[9]),  "=r"(r[10]), "=r"(r[11]),
          "=r"(r[12]), "=r"(r[13]), "=r"(r[14]), "=r"(r[15]),
          "=r"(r[16]), "=r"(r[17]), "=r"(r[18]), "=r"(r[19]),
          "=r"(r[20]), "=r"(r[21]), "=r"(r[22]), "=r"(r[23]),
          "=r"(r[24]), "=r"(r[25]), "=r"(r[26]), "=r"(r[27]),
          "=r"(r[28]), "=r"(r[29]), "=r"(r[30]), "=r"(r[31])
        : "r"(a));
#else
#pragma unroll
    for (int i = 0; i < 32; ++i) r[i] = 0u;
    (void)a;
#endif
}

// ---------------------------------------------------------------------------
// Load one K-chunk (32 floats) of A(128 rows) + B(BN rows), K-major, SW128.
// 256 threads; each cp.async moves 16B.
// ---------------------------------------------------------------------------
template <int BN>
__device__ __forceinline__ void load_chunk(u32 st, const float* A, const float* B,
                                           int bm, int bn, int kt, int lda, int ldb, int tid)
{
#pragma unroll
    for (int i = 0; i < 4; ++i) {                     // A: 1024 x 16B
        int o = tid + (i << 8);
        int r = o >> 3, c = o & 7;
        cp16(st + swz((u32)((r << 7) + (c << 4))),
             A + (size_t)(bm + r) * lda + kt + (c << 2));
    }
    const u32 stB = st + 128 * 128;
#pragma unroll
    for (int i = 0; i < BN / 32; ++i) {               // B: BN*8 x 16B
        int o = tid + (i << 8);
        int r = o >> 3, c = o & 7;
        cp16(stB + swz((u32)((r << 7) + (c << 4))),
             B + (size_t)(bn + r) * ldb + kt + (c << 2));
    }
}

// ---------------------------------------------------------------------------
// tcgen05 tf32 SS GEMM (NT): C[m,n] = sum_k A[m,k]*B[n,k]  (+bias)(+res/gate)
// CTA tile 128 x BN. Grid: (N/BN, M/128, batch). K % 32 == 0.
// Rows >= Mstore are computed but not stored.
// ---------------------------------------------------------------------------
template <int BN, int STAGES, int EPI>
__global__ __launch_bounds__(256, 1)
void tc_gemm(const float* __restrict__ A, const float* __restrict__ B, float* __restrict__ C,
             int K, int lda, int ldb, int ldc,
             size_t sA, size_t sB, size_t sC,
             const float* __restrict__ bias,
             const float* __restrict__ res, int ldres,
             const float* __restrict__ gate, int Mstore)
{
    constexpr int ASZ = 128 * 128;
    constexpr int BSZ = BN * 128;
    constexpr int STRIDE = ASZ + BSZ;
    constexpr u32 IDESC = (1u << 4) | (2u << 7) | (2u << 10) |
                          ((u32)(BN / 8) << 17) | (8u << 24);

    extern __shared__ char smem[];
    const u32 sb = s2u(smem);
    const u32 mb0 = sb + 8;
    const u32 tile0 = sb + 1024;

    A += (size_t)blockIdx.z * sA;
    B += (size_t)blockIdx.z * sB;
    C += (size_t)blockIdx.z * sC;
    const int bm = blockIdx.y * 128;
    const int bn = blockIdx.x * BN;
    const int tid = threadIdx.x;

    if (tid == 0)
        for (int s = 0; s < STAGES; ++s) mbar_init(mb0 + 8 * s);
    if (tid < 32) {
        tmem_alloc(sb, BN);
        tmem_relinquish();
    }
    __syncthreads();
    u32 tmem;
    asm volatile("ld.shared.b32 %0, [%1];" : "=r"(tmem) : "r"(sb));

    const int nk = K >> 5;

    // prologue: prefetch STAGES-1 chunks
    for (int p = 0; p < STAGES - 1; ++p) {
        if (p < nk)
            load_chunk<BN>(tile0 + (p % STAGES) * STRIDE, A, B, bm, bn, p << 5, lda, ldb, tid);
        cp_commit();
    }

    for (int it = 0; it < nk; ++it) {
        const int b = it % STAGES;
        cp_wait<STAGES - 2>();           // chunk 'it' resident (mine)
        fence_async_shared();
        __syncthreads();                 // chunk 'it' resident (everyone)

        if (tid < 32) {
            u64 da = sdesc(tile0 + b * STRIDE);
            u64 db = sdesc(tile0 + b * STRIDE + ASZ);
            if (elect1()) {
#pragma unroll
                for (int j = 0; j < 4; ++j)
                    mma_tf32(tmem, da + j * 2, db + j * 2, IDESC,
                             (u32)((it > 0) || (j > 0)));
                tc_commit(mb0 + 8 * b);
            }
        }

        const int p = it + STAGES - 1;   // prefetch into stage (it-1)%STAGES
        if (p < nk) {
            if (it >= 1)
                mbar_wait(mb0 + 8 * (p % STAGES), (u32)(((it - 1) / STAGES) & 1));
            load_chunk<BN>(tile0 + (p % STAGES) * STRIDE, A, B, bm, bn, p << 5, lda, ldb, tid);
        }
        cp_commit();                     // always commit (keeps group math valid)
    }

    mbar_wait(mb0 + 8 * ((nk - 1) % STAGES), (u32)(((nk - 1) / STAGES) & 1));
    tc_fence_after();

    if (tid < 128) {
        const int w = tid >> 5, lane = tid & 31;
        const int row = bm + w * 32 + lane;
        const bool doSt = row < Mstore;
        float* crow = C + (size_t)row * ldc;
        const float* rrow = (EPI && doSt) ? (res + (size_t)row * ldres) : nullptr;
#pragma unroll
        for (int g = 0; g < BN / 32; ++g) {
            u32 regs[32];
            ldtm32(regs, tmem + g * 32);     // warp-collective: no divergence here
            tmem_wait_ld();
            if (doSt) {
#pragma unroll
                for (int q4 = 0; q4 < 8; ++q4) {
                    int col = bn + g * 32 + q4 * 4;
                    float4 vv;
                    vv.x = __uint_as_float(regs[q4 * 4 + 0]);
                    vv.y = __uint_as_float(regs[q4 * 4 + 1]);
                    vv.z = __uint_as_float(regs[q4 * 4 + 2]);
                    vv.w = __uint_as_float(regs[q4 * 4 + 3]);
                    if (bias) {
                        float4 bb = *(const float4*)(bias + col);
                        vv.x += bb.x; vv.y += bb.y; vv.z += bb.z; vv.w += bb.w;
                    }
                    if (EPI) {
                        float4 rr = *(const float4*)(rrow + col);
                        float4 gg = *(const float4*)(gate + col);
                        vv.x = rr.x + gg.x * vv.x;
                        vv.y = rr.y + gg.y * vv.y;
                        vv.z = rr.z + gg.z * vv.z;
                        vv.w = rr.w + gg.w * vv.w;
                    }
                    *(float4*)(crow + col) = vv;
                }
            }
        }
    }
    __syncthreads();
    if (tid < 32) tmem_dealloc(tmem, BN);
}

// ---------------------------------------------------------------------------
// m = silu(vec) @ mod_w.T + mod_b
// ---------------------------------------------------------------------------
__global__ void mod_kernel(const float* __restrict__ vec, const float* __restrict__ mw,
                           const float* __restrict__ mb, float* __restrict__ m)
{
    int o = blockIdx.x, t = threadIdx.x;
    float s = 0.f;
    for (int k = t; k < HID; k += 256) {
        float v = vec[k];
        s += (v / (1.f + expf(-v))) * mw[(size_t)o * HID + k];
    }
    __shared__ float red[256];
    red[t] = s; __syncthreads();
    for (int st = 128; st > 0; st >>= 1) { if (t < st) red[t] += red[t + st]; __syncthreads(); }
    if (t == 0) m[o] = red[0] + mb[o];
}

// ---------------------------------------------------------------------------
// xm = (1 + scale) * LayerNorm(in) + shift
// ---------------------------------------------------------------------------
__global__ void ln_mod_kernel(const float* __restrict__ in, float* __restrict__ out,
                              const float* __restrict__ m)
{
    int row = blockIdx.x, t = threadIdx.x;
    const float* x = in + (size_t)row * HID;
    __shared__ float buf[HID];
    __shared__ float red[256];

    float s = 0.f;
    for (int c = t; c < HID; c += 256) { float v = x[c]; buf[c] = v; s += v; }
    red[t] = s; __syncthreads();
    for (int st = 128; st > 0; st >>= 1) { if (t < st) red[t] += red[t + st]; __syncthreads(); }
    float mu = red[0] * (1.f / HID);
    __syncthreads();

    float ss = 0.f;
    for (int c = t; c < HID; c += 256) { float d = buf[c] - mu; ss += d * d; }
    red[t] = ss; __syncthreads();
    for (int st = 128; st > 0; st >>= 1) { if (t < st) red[t] += red[t + st]; __syncthreads(); }
    float inv = rsqrtf(red[0] * (1.f / HID) + 1e-6f);

    float* o = out + (size_t)row * HID;
    for (int c = t; c < HID; c += 256)
        o[c] = (1.f + m[HID + c]) * ((buf[c] - mu) * inv) + m[c];
}

// ---------------------------------------------------------------------------
// Per-(token, head): optional rmsnorm + optional RoPE; write head-major
// [h][l][d] (transp=0) or transposed [h][d][l] (transp=1).
// ---------------------------------------------------------------------------
__global__ void rmsrope_kernel(const float* __restrict__ src, int ldh,
                               const float* __restrict__ pe,
                               const float* __restrict__ scale, int dorope,
                               float* __restrict__ dst, int dstL, int transp)
{
    int l = blockIdx.x, hd = blockIdx.y, d = threadIdx.x;   // 128 threads
    float v = src[(size_t)l * ldh + hd * HD + d];
    __shared__ float sv[HD];
    __shared__ float wred[4];

    if (scale) {
        float ss = v * v;
#pragma unroll
        for (int o = 16; o > 0; o >>= 1) ss += __shfl_xor_sync(0xffffffffu, ss, o);
        if ((d & 31) == 0) wred[d >> 5] = ss;
        __syncthreads();
        float tot = wred[0] + wred[1] + wred[2] + wred[3];
        v = v * rsqrtf(tot * (1.f / HD) + 1e-6f) * scale[d];
        __syncthreads();
    }
    float outv;
    if (dorope) {
        sv[d] = v; __syncthreads();
        int i = d >> 1, j = d & 1;
        const float* pp = pe + (size_t)l * 256 + i * 4 + j * 2;
        outv = pp[0] * sv[2 * i] + pp[1] * sv[2 * i + 1];
    } else {
        outv = v;
    }
    if (transp)
        dst[((size_t)hd * HD + d) * dstL + l] = outv;
    else
        dst[((size_t)hd * dstL + l) * HD + d] = outv;
}

// ---------------------------------------------------------------------------
// Row softmax with pre-scale; zeroes padded cols >= Nvalid.
// ---------------------------------------------------------------------------
__global__ void softmax_kernel(float* __restrict__ S, int rowStride,
                               int Npad, int Nvalid, float scale)
{
    int row = blockIdx.x, head = blockIdx.y, t = threadIdx.x;
    float* p = S + ((size_t)head * rowStride + row) * Npad;
    __shared__ float srow[LX];
    __shared__ float red[256];

    float mx = -1e30f;
    for (int j = t; j < Nvalid; j += 256) {
        float v = p[j] * scale;
        srow[j] = v;
        mx = fmaxf(mx, v);
    }
    red[t] = mx; __syncthreads();
    for (int st = 128; st > 0; st >>= 1) { if (t < st) red[t] = fmaxf(red[t], red[t + st]); __syncthreads(); }
    mx = red[0];
    __syncthreads();

    float sum = 0.f;
    for (int j = t; j < Nvalid; j += 256) {
        float e = __expf(srow[j] - mx);
        srow[j] = e;
        sum += e;
    }
    red[t] = sum; __syncthreads();
    for (int st = 128; st > 0; st >>= 1) { if (t < st) red[t] += red[t + st]; __syncthreads(); }
    float inv = 1.f / red[0];

    for (int j = t; j < Nvalid; j += 256) p[j] = srow[j] * inv;
    for (int j = Nvalid + t; j < Npad; j += 256) p[j] = 0.f;
}

// ---------------------------------------------------------------------------
// cat[l][0:1536] = attn (from head-major O), cat[l][1536:] = gelu(mlp)
// ---------------------------------------------------------------------------
__global__ void cat_kernel(const float* __restrict__ O, int OL,
                           const float* __restrict__ mlp, int ldm,
                           float* __restrict__ cat)
{
    int l = blockIdx.y;
    int c = blockIdx.x * 256 + threadIdx.x;
    float v;
    if (c < HID) {
        int hd = c >> 7, d = c & 127;
        v = O[((size_t)hd * OL + l) * HD + d];
    } else {
        float xg = mlp[(size_t)l * ldm + (c - HID)];
        float u = 0.7978845608028654f * (xg + 0.044715f * xg * xg * xg);
        v = 0.5f * xg * (1.f + tanhf(u));
    }
    cat[(size_t)l * CATW + c] = v;
}

// ---------------------------------------------------------------------------
// kernel_launch
// ---------------------------------------------------------------------------
#define SMEM_FOR(BN, S) (1024 + (S) * ((128 * 128) + (BN) * 128))

extern "C" void kernel_launch(void* const* d_in, const int* in_sizes, int n_in,
                              void* d_out, int out_size)
{
    (void)in_sizes; (void)n_in; (void)out_size;
    const float* x   = (const float*)d_in[0];
    const float* cps = (const float*)d_in[1];
    const float* vec = (const float*)d_in[2];
    const float* pe  = (const float*)d_in[3];
    const float* cpe = (const float*)d_in[4];
    const float* w1  = (const float*)d_in[5];
    const float* b1  = (const float*)d_in[6];
    const float* w2  = (const float*)d_in[7];
    const float* b2  = (const float*)d_in[8];
    const float* qs  = (const float*)d_in[9];
    const float* ks  = (const float*)d_in[10];
    const float* mw  = (const float*)d_in[11];
    const float* mb  = (const float*)d_in[12];
    float* out = (float*)d_out;

    const int SM256 = SMEM_FOR(256, 4);
    const int SM128 = SMEM_FOR(128, 6);
    cudaFuncSetAttribute(tc_gemm<256, 4, 0>, cudaFuncAttributeMaxDynamicSharedMemorySize, SM256);
    cudaFuncSetAttribute(tc_gemm<256, 4, 1>, cudaFuncAttributeMaxDynamicSharedMemorySize, SM256);
    cudaFuncSetAttribute(tc_gemm<128, 6, 0>, cudaFuncAttributeMaxDynamicSharedMemorySize, SM128);

    float *m, *xm, *h, *h2kv, *h2f, *q, *k, *v, *q2, *k2, *v2, *S, *S2, *O, *O2, *cat, *cat2;
    cudaGetSymbolAddress((void**)&m,    g_m);
    cudaGetSymbolAddress((void**)&xm,   g_xm);
    cudaGetSymbolAddress((void**)&h,    g_h);
    cudaGetSymbolAddress((void**)&h2kv, g_h2kv);
    cudaGetSymbolAddress((void**)&h2f,  g_h2f);
    cudaGetSymbolAddress((void**)&q,    g_q);
    cudaGetSymbolAddress((void**)&k,    g_k);
    cudaGetSymbolAddress((void**)&v,    g_v);
    cudaGetSymbolAddress((void**)&q2,   g_q2);
    cudaGetSymbolAddress((void**)&k2,   g_k2);
    cudaGetSymbolAddress((void**)&v2,   g_v2);
    cudaGetSymbolAddress((void**)&S,    g_S);
    cudaGetSymbolAddress((void**)&S2,   g_S2);
    cudaGetSymbolAddress((void**)&O,    g_O);
    cudaGetSymbolAddress((void**)&O2,   g_O2);
    cudaGetSymbolAddress((void**)&cat,  g_cat);
    cudaGetSymbolAddress((void**)&cat2, g_cat2);

    mod_kernel<<<3 * HID, 256>>>(vec, mw, mb, m);

    // ================= Block 1 (L = 4352) =================
    ln_mod_kernel<<<LX, 256>>>(x, xm, m);

    // h = xm @ w1.T + b1
    tc_gemm<256, 4, 0><<<dim3(W1ROWS / 256, LX / 128, 1), 256, SM256>>>(
        xm, w1, h, HID, HID, HID, W1ROWS, 0, 0, 0, b1, nullptr, 0, nullptr, LX);

    dim3 gqk(LX, NH);
    rmsrope_kernel<<<gqk, HD>>>(h + 0,       W1ROWS, pe, qs,      1, q, LX, 0);
    rmsrope_kernel<<<gqk, HD>>>(h + HID,     W1ROWS, pe, ks,      1, k, LX, 0);
    rmsrope_kernel<<<gqk, HD>>>(h + 2 * HID, W1ROWS, pe, nullptr, 0, v, LX, 1);  // vT

    // S = q @ k^T
    tc_gemm<256, 4, 0><<<dim3(LX / 256, LX / 128, NH), 256, SM256>>>(
        q, k, S, HD, HD, HD, LX,
        (size_t)LX * HD, (size_t)LX * HD, (size_t)LX * LX,
        nullptr, nullptr, 0, nullptr, LX);

    softmax_kernel<<<dim3(LX, NH), 256>>>(S, LX, LX, LX, SOFT_SCALE);

    // O = P @ V   (B = vT, NT)
    tc_gemm<128, 6, 0><<<dim3(1, LX / 128, NH), 256, SM128>>>(
        S, v, O, LX, LX, LX, HD,
        (size_t)LX * LX, (size_t)HD * LX, (size_t)LX * HD,
        nullptr, nullptr, 0, nullptr, LX);

    cat_kernel<<<dim3(CATW / 256, LX), 256>>>(O, LX, h + 3 * HID, W1ROWS, cat);

    // out_x = x + gate * (cat @ w2.T + b2)
    tc_gemm<256, 4, 1><<<dim3(HID / 256, LX / 128, 1), 256, SM256>>>(
        cat, w2, out, CATW, CATW, CATW, HID, 0, 0, 0, b2, x, HID, m + 2 * HID, LX);

    // ================= Block 2 (L = 4116, only 20 output rows kept) =========
    ln_mod_kernel<<<NC, 256>>>(cps, xm, m);
    ln_mod_kernel<<<4096, 256>>>(x + (size_t)256 * HID, xm + (size_t)NC * HID, m);

    // k,v for all rows (w1 cols 1536..4607); padded M rows read stale xm (deterministic)
    tc_gemm<256, 4, 0><<<dim3(3072 / 256, L2P / 128, 1), 256, SM256>>>(
        xm, w1 + (size_t)HID * HID, h2kv, HID, HID, HID, 3072,
        0, 0, 0, b1 + HID, nullptr, 0, nullptr, L2P);

    // full h (q + mlp) for first 128 rows (only 20 used)
    tc_gemm<256, 4, 0><<<dim3(W1ROWS / 256, 1, 1), 256, SM256>>>(
        xm, w1, h2f, HID, HID, HID, W1ROWS, 0, 0, 0, b1, nullptr, 0, nullptr, 128);

    dim3 gk2(L2V, NH);
    rmsrope_kernel<<<gk2, HD>>>(h2kv + 0,   3072, cpe, ks,      1, k2, L2P, 0);
    rmsrope_kernel<<<gk2, HD>>>(h2kv + HID, 3072, cpe, nullptr, 0, v2, L2P, 1);  // vT
    rmsrope_kernel<<<dim3(NC, NH), HD>>>(h2f + 0, W1ROWS, cpe, qs, 1, q2, 128, 0);

    tc_gemm<256, 4, 0><<<dim3(L2P / 256, 1, NH), 256, SM256>>>(
        q2, k2, S2, HD, HD, HD, L2P,
        (size_t)128 * HD, (size_t)L2P * HD, (size_t)128 * L2P,
        nullptr, nullptr, 0, nullptr, 128);

    softmax_kernel<<<dim3(NC, NH), 256>>>(S2, 128, L2P, L2V, SOFT_SCALE);

    tc_gemm<128, 6, 0><<<dim3(1, 1, NH), 256, SM128>>>(
        S2, v2, O2, L2P, L2P, L2P, HD,
        (size_t)128 * L2P, (size_t)HD * L2P, (size_t)128 * HD,
        nullptr, nullptr, 0, nullptr, 128);

    cat_kernel<<<dim3(CATW / 256, NC), 256>>>(O2, 128, h2f + 3 * HID, W1ROWS, cat2);

    // concepts_out = concepts + gate * (cat2 @ w2.T + b2)   (store 20 rows only)
    tc_gemm<256, 4, 1><<<dim3(HID / 256, 1, 1), 256, SM256>>>(
        cat2, w2, out + (size_t)LX * HID, CATW, CATW, CATW, HID,
        0, 0, 0, b2, cps, HID, m + 2 * HID, NC);
}

// round 6
// speedup vs baseline: 5.7376x; 1.4852x over previous
#include <cuda_runtime.h>
#include <cuda_bf16.h>
#include <cstdint>
#include <cstddef>

// ---------------------------------------------------------------------------
// Problem constants
// ---------------------------------------------------------------------------
#define HID     1536
#define NH      12
#define HD      128
#define MLP     6144
#define LX      4352          // 256 + 4096
#define NC      20
#define L2V     4116          // 20 + 4096 (valid rows, block 2)
#define L2P     4352          // padded to multiple of 256
#define W1ROWS  10752         // 3*HID + MLP
#define CATW    7680          // HID + MLP
#define SOFT_SCALE 0.08838834764831845f   // 1/sqrt(128)

typedef unsigned int u32;
typedef unsigned long long u64;

// tcgen05 exists only in the 'a' (arch-accelerated) targets. The harness also
// compiles a plain compute_103 pass; these instructions must vanish there.
#if defined(__CUDA_ARCH_FEAT_SM103_ALL) || defined(__CUDA_ARCH_FEAT_SM100_ALL) || defined(__CUDA_ARCH_FEAT_SM101_ALL)
#define HAS_TCGEN05 1
#else
#define HAS_TCGEN05 0
#endif

// ---------------------------------------------------------------------------
// Scratch (device globals; zero-initialized; rows never written stay zero)
// ---------------------------------------------------------------------------
__device__ __align__(256) float g_m[3 * HID];
__device__ __align__(256) float g_xm[(size_t)LX * HID];
__device__ __align__(256) float g_h[(size_t)LX * W1ROWS];
__device__ __align__(256) float g_h2kv[(size_t)L2P * 3072];
__device__ __align__(256) float g_h2f[(size_t)128 * W1ROWS];
__device__ __align__(256) float g_q[(size_t)NH * LX * HD];
__device__ __align__(256) float g_k[(size_t)NH * LX * HD];
__device__ __align__(256) float g_v[(size_t)NH * HD * LX];      // vT: [h][d][l]
__device__ __align__(256) float g_q2[(size_t)NH * 128 * HD];
__device__ __align__(256) float g_k2[(size_t)NH * L2P * HD];
__device__ __align__(256) float g_v2[(size_t)NH * HD * L2P];    // vT
__device__ __align__(256) float g_S[(size_t)NH * LX * LX];      // ~909 MB
__device__ __align__(256) float g_S2[(size_t)NH * 128 * L2P];
__device__ __align__(256) float g_O[(size_t)NH * LX * HD];
__device__ __align__(256) float g_O2[(size_t)NH * 128 * HD];
__device__ __align__(256) float g_cat[(size_t)LX * CATW];
__device__ __align__(256) float g_cat2[(size_t)128 * CATW];

// ---------------------------------------------------------------------------
// PTX helpers
// ---------------------------------------------------------------------------
__device__ __forceinline__ u32 s2u(const void* p) {
    return (u32)__cvta_generic_to_shared(p);
}
__device__ __forceinline__ u32 swz(u32 o) { return o ^ ((o >> 3) & 0x70); }

__device__ __forceinline__ void cp16(u32 dst, const void* src) {
    asm volatile("cp.async.cg.shared.global [%0], [%1], 16;" :: "r"(dst), "l"(src));
}
__device__ __forceinline__ void cp_commit() {
    asm volatile("cp.async.commit_group;" ::: "memory");
}
template <int N> __device__ __forceinline__ void cp_wait() {
    asm volatile("cp.async.wait_group %0;" :: "n"(N) : "memory");
}
__device__ __forceinline__ bool elect1() {
    u32 p;
    asm volatile("{\n\t.reg .pred p;\n\telect.sync _|p, 0xFFFFFFFF;\n\tselp.b32 %0,1,0,p;\n\t}"
                 : "=r"(p));
    return p != 0;
}
// SW128 K-major descriptor: layout=SW128, version=1, SBO=64 (1024B), LBO=1 (16B)
__device__ __forceinline__ u64 sdesc(u32 addr) {
    return 0x4000404000010000ull | (u64)((addr >> 4) & 0x3FFF);
}
__device__ __forceinline__ void mbar_init(u32 a) {
    u32 one = 1;
    asm volatile("mbarrier.init.shared.b64 [%0], %1;" :: "r"(a), "r"(one) : "memory");
}
__device__ __forceinline__ void mbar_wait(u32 a, u32 parity) {
    asm volatile(
        "{\n\t.reg .pred P;\n"
        "LW_%=:\n\t"
        "mbarrier.try_wait.parity.acquire.cta.shared::cta.b64 P, [%0], %1, 0x989680;\n\t"
        "@P bra LD_%=;\n\t"
        "bra LW_%=;\n"
        "LD_%=:\n\t}"
        :: "r"(a), "r"(parity) : "memory");
}
__device__ __forceinline__ void fence_async_shared() {
    asm volatile("fence.proxy.async.shared::cta;" ::: "memory");
}

// ---- tcgen05 family (guarded: only real on sm_103a-class targets) ---------
__device__ __forceinline__ void tc_commit(u32 mbar) {
#if HAS_TCGEN05
    asm volatile(
        "tcgen05.commit.cta_group::1.mbarrier::arrive::one.shared::cluster.b64 [%0];"
        :: "r"(mbar) : "memory");
#else
    (void)mbar;
#endif
}
__device__ __forceinline__ void mma_tf32(u32 d, u64 ad, u64 bd, u32 idesc, u32 en) {
#if HAS_TCGEN05
    asm volatile(
        "{\n\t.reg .pred p;\n\tsetp.ne.u32 p, %4, 0;\n\t"
        "tcgen05.mma.cta_group::1.kind::tf32 [%0], %1, %2, %3, {%5,%5,%5,%5}, p;\n\t}"
        :: "r"(d), "l"(ad), "l"(bd), "r"(idesc), "r"(en), "r"(0u) : "memory");
#else
    (void)d; (void)ad; (void)bd; (void)idesc; (void)en;
#endif
}
__device__ __forceinline__ void tc_fence_after() {
#if HAS_TCGEN05
    asm volatile("tcgen05.fence::after_thread_sync;" ::: "memory");
#endif
}
__device__ __forceinline__ void tmem_alloc(u32 dst_smem, u32 ncols) {
#if HAS_TCGEN05
    asm volatile("tcgen05.alloc.cta_group::1.sync.aligned.shared::cta.b32 [%0], %1;"
                 :: "r"(dst_smem), "r"(ncols) : "memory");
#else
    (void)dst_smem; (void)ncols;
#endif
}
__device__ __forceinline__ void tmem_relinquish() {
#if HAS_TCGEN05
    asm volatile("tcgen05.relinquish_alloc_permit.cta_group::1.sync.aligned;");
#endif
}
__device__ __forceinline__ void tmem_dealloc(u32 tmem, u32 ncols) {
#if HAS_TCGEN05
    asm volatile("tcgen05.dealloc.cta_group::1.sync.aligned.b32 %0, %1;" :: "r"(tmem), "r"(ncols));
#else
    (void)tmem; (void)ncols;
#endif
}
__device__ __forceinline__ void tmem_wait_ld() {
#if HAS_TCGEN05
    asm volatile("tcgen05.wait::ld.sync.aligned;" ::: "memory");
#endif
}
__device__ __forceinline__ void ldtm32(u32* r, u32 a) {
#if HAS_TCGEN05
    asm volatile(
        "tcgen05.ld.sync.aligned.32x32b.x32.b32 "
        "{%0, %1, %2, %3, %4, %5, %6, %7, "
        " %8, %9, %10, %11, %12, %13, %14, %15, "
        " %16, %17, %18, %19, %20, %21, %22, %23, "
        " %24, %25, %26, %27, %28, %29, %30, %31}, [%32];"
        : "=r"(r[0]),  "=r"(r[1]),  "=r"(r[2]),  "=r"(r[3]),
          "=r"(r[4]),  "=r"(r[5]),  "=r"(r[6]),  "=r"(r[7]),
          "=r"(r[8]),  "=r"(r[9]),  "=r"(r[10]), "=r"(r[11]),
          "=r"(r[12]), "=r"(r[13]), "=r"(r[14]), "=r"(r[15]),
          "=r"(r[16]), "=r"(r[17]), "=r"(r[18]), "=r"(r[19]),
          "=r"(r[20]), "=r"(r[21]), "=r"(r[22]), "=r"(r[23]),
          "=r"(r[24]), "=r"(r[25]), "=r"(r[26]), "=r"(r[27]),
          "=r"(r[28]), "=r"(r[29]), "=r"(r[30]), "=r"(r[31])
        : "r"(a));
#else
#pragma unroll
    for (int i = 0; i < 32; ++i) r[i] = 0u;
    (void)a;
#endif
}

// ---------------------------------------------------------------------------
// Load one K-chunk (32 floats) of A(128 rows) + B(BN rows), K-major, SW128.
// 256 threads; each cp.async moves 16B.
// ---------------------------------------------------------------------------
template <int BN>
__device__ __forceinline__ void load_chunk(u32 st, const float* A, const float* B,
                                           int bm, int bn, int kt, int lda, int ldb, int tid)
{
#pragma unroll
    for (int i = 0; i < 4; ++i) {                     // A: 1024 x 16B
        int o = tid + (i << 8);
        int r = o >> 3, c = o & 7;
        cp16(st + swz((u32)((r << 7) + (c << 4))),
             A + (size_t)(bm + r) * lda + kt + (c << 2));
    }
    const u32 stB = st + 128 * 128;
#pragma unroll
    for (int i = 0; i < BN / 32; ++i) {               // B: BN*8 x 16B
        int o = tid + (i << 8);
        int r = o >> 3, c = o & 7;
        cp16(stB + swz((u32)((r << 7) + (c << 4))),
             B + (size_t)(bn + r) * ldb + kt + (c << 2));
    }
}

// ---------------------------------------------------------------------------
// tcgen05 tf32 SS GEMM (NT): C[m,n] = sum_k A[m,k]*B[n,k]  (+bias)(+res/gate)
// CTA tile 128 x BN. Grid: (N/BN, M/128, batch). K % 32 == 0.
// Rows >= Mstore are computed but not stored.
// ---------------------------------------------------------------------------
template <int BN, int STAGES, int EPI>
__global__ __launch_bounds__(256, 1)
void tc_gemm(const float* __restrict__ A, const float* __restrict__ B, float* __restrict__ C,
             int K, int lda, int ldb, int ldc,
             size_t sA, size_t sB, size_t sC,
             const float* __restrict__ bias,
             const float* __restrict__ res, int ldres,
             const float* __restrict__ gate, int Mstore)
{
    constexpr int ASZ = 128 * 128;
    constexpr int BSZ = BN * 128;
    constexpr int STRIDE = ASZ + BSZ;
    constexpr u32 IDESC = (1u << 4) | (2u << 7) | (2u << 10) |
                          ((u32)(BN / 8) << 17) | (8u << 24);

    extern __shared__ char smem[];
    const u32 sb = s2u(smem);
    const u32 mb0 = sb + 8;
    const u32 tile0 = sb + 1024;

    A += (size_t)blockIdx.z * sA;
    B += (size_t)blockIdx.z * sB;
    C += (size_t)blockIdx.z * sC;
    const int bm = blockIdx.y * 128;
    const int bn = blockIdx.x * BN;
    const int tid = threadIdx.x;

    if (tid == 0)
        for (int s = 0; s < STAGES; ++s) mbar_init(mb0 + 8 * s);
    if (tid < 32) {
        tmem_alloc(sb, BN);
        tmem_relinquish();
    }
    __syncthreads();
    u32 tmem;
    asm volatile("ld.shared.b32 %0, [%1];" : "=r"(tmem) : "r"(sb));

    const int nk = K >> 5;

    // prologue: prefetch STAGES-1 chunks
    for (int p = 0; p < STAGES - 1; ++p) {
        if (p < nk)
            load_chunk<BN>(tile0 + (p % STAGES) * STRIDE, A, B, bm, bn, p << 5, lda, ldb, tid);
        cp_commit();
    }

    for (int it = 0; it < nk; ++it) {
        const int b = it % STAGES;
        cp_wait<STAGES - 2>();           // chunk 'it' resident (mine)
        fence_async_shared();
        __syncthreads();                 // chunk 'it' resident (everyone)

        if (tid < 32) {
            u64 da = sdesc(tile0 + b * STRIDE);
            u64 db = sdesc(tile0 + b * STRIDE + ASZ);
            if (elect1()) {
#pragma unroll
                for (int j = 0; j < 4; ++j)
                    mma_tf32(tmem, da + j * 2, db + j * 2, IDESC,
                             (u32)((it > 0) || (j > 0)));
                tc_commit(mb0 + 8 * b);
            }
        }

        const int p = it + STAGES - 1;   // prefetch into stage (it-1)%STAGES
        if (p < nk) {
            if (it >= 1)
                mbar_wait(mb0 + 8 * (p % STAGES), (u32)(((it - 1) / STAGES) & 1));
            load_chunk<BN>(tile0 + (p % STAGES) * STRIDE, A, B, bm, bn, p << 5, lda, ldb, tid);
        }
        cp_commit();                     // always commit (keeps group math valid)
    }

    mbar_wait(mb0 + 8 * ((nk - 1) % STAGES), (u32)(((nk - 1) / STAGES) & 1));
    tc_fence_after();

    if (tid < 128) {
        const int w = tid >> 5, lane = tid & 31;
        const int row = bm + w * 32 + lane;
        const bool doSt = row < Mstore;
        float* crow = C + (size_t)row * ldc;
        const float* rrow = (EPI && doSt) ? (res + (size_t)row * ldres) : nullptr;
#pragma unroll
        for (int g = 0; g < BN / 32; ++g) {
            u32 regs[32];
            ldtm32(regs, tmem + g * 32);     // warp-collective: no divergence here
            tmem_wait_ld();
            if (doSt) {
#pragma unroll
                for (int q4 = 0; q4 < 8; ++q4) {
                    int col = bn + g * 32 + q4 * 4;
                    float4 vv;
                    vv.x = __uint_as_float(regs[q4 * 4 + 0]);
                    vv.y = __uint_as_float(regs[q4 * 4 + 1]);
                    vv.z = __uint_as_float(regs[q4 * 4 + 2]);
                    vv.w = __uint_as_float(regs[q4 * 4 + 3]);
                    if (bias) {
                        float4 bb = *(const float4*)(bias + col);
                        vv.x += bb.x; vv.y += bb.y; vv.z += bb.z; vv.w += bb.w;
                    }
                    if (EPI) {
                        float4 rr = *(const float4*)(rrow + col);
                        float4 gg = *(const float4*)(gate + col);
                        vv.x = rr.x + gg.x * vv.x;
                        vv.y = rr.y + gg.y * vv.y;
                        vv.z = rr.z + gg.z * vv.z;
                        vv.w = rr.w + gg.w * vv.w;
                    }
                    *(float4*)(crow + col) = vv;
                }
            }
        }
    }
    __syncthreads();
    if (tid < 32) tmem_dealloc(tmem, BN);
}

// ---------------------------------------------------------------------------
// m = silu(vec) @ mod_w.T + mod_b
// ---------------------------------------------------------------------------
__global__ void mod_kernel(const float* __restrict__ vec, const float* __restrict__ mw,
                           const float* __restrict__ mb, float* __restrict__ m)
{
    int o = blockIdx.x, t = threadIdx.x;
    float s = 0.f;
    for (int k = t; k < HID; k += 256) {
        float v = vec[k];
        s += (v / (1.f + expf(-v))) * mw[(size_t)o * HID + k];
    }
    __shared__ float red[256];
    red[t] = s; __syncthreads();
    for (int st = 128; st > 0; st >>= 1) { if (t < st) red[t] += red[t + st]; __syncthreads(); }
    if (t == 0) m[o] = red[0] + mb[o];
}

// ---------------------------------------------------------------------------
// xm = (1 + scale) * LayerNorm(in) + shift
// ---------------------------------------------------------------------------
__global__ void ln_mod_kernel(const float* __restrict__ in, float* __restrict__ out,
                              const float* __restrict__ m)
{
    int row = blockIdx.x, t = threadIdx.x;
    const float* x = in + (size_t)row * HID;
    __shared__ float buf[HID];
    __shared__ float red[256];

    float s = 0.f;
    for (int c = t; c < HID; c += 256) { float v = x[c]; buf[c] = v; s += v; }
    red[t] = s; __syncthreads();
    for (int st = 128; st > 0; st >>= 1) { if (t < st) red[t] += red[t + st]; __syncthreads(); }
    float mu = red[0] * (1.f / HID);
    __syncthreads();

    float ss = 0.f;
    for (int c = t; c < HID; c += 256) { float d = buf[c] - mu; ss += d * d; }
    red[t] = ss; __syncthreads();
    for (int st = 128; st > 0; st >>= 1) { if (t < st) red[t] += red[t + st]; __syncthreads(); }
    float inv = rsqrtf(red[0] * (1.f / HID) + 1e-6f);

    float* o = out + (size_t)row * HID;
    for (int c = t; c < HID; c += 256)
        o[c] = (1.f + m[HID + c]) * ((buf[c] - mu) * inv) + m[c];
}

// ---------------------------------------------------------------------------
// Per-(token, head): optional rmsnorm + optional RoPE; write head-major
// [h][l][d] (transp=0) or transposed [h][d][l] (transp=1).
// ---------------------------------------------------------------------------
__global__ void rmsrope_kernel(const float* __restrict__ src, int ldh,
                               const float* __restrict__ pe,
                               const float* __restrict__ scale, int dorope,
                               float* __restrict__ dst, int dstL, int transp)
{
    int l = blockIdx.x, hd = blockIdx.y, d = threadIdx.x;   // 128 threads
    float v = src[(size_t)l * ldh + hd * HD + d];
    __shared__ float sv[HD];
    __shared__ float wred[4];

    if (scale) {
        float ss = v * v;
#pragma unroll
        for (int o = 16; o > 0; o >>= 1) ss += __shfl_xor_sync(0xffffffffu, ss, o);
        if ((d & 31) == 0) wred[d >> 5] = ss;
        __syncthreads();
        float tot = wred[0] + wred[1] + wred[2] + wred[3];
        v = v * rsqrtf(tot * (1.f / HD) + 1e-6f) * scale[d];
        __syncthreads();
    }
    float outv;
    if (dorope) {
        sv[d] = v; __syncthreads();
        int i = d >> 1, j = d & 1;
        const float* pp = pe + (size_t)l * 256 + i * 4 + j * 2;
        outv = pp[0] * sv[2 * i] + pp[1] * sv[2 * i + 1];
    } else {
        outv = v;
    }
    if (transp)
        dst[((size_t)hd * HD + d) * dstL + l] = outv;
    else
        dst[((size_t)hd * dstL + l) * HD + d] = outv;
}

// ---------------------------------------------------------------------------
// Row softmax with pre-scale; zeroes padded cols >= Nvalid.
// ---------------------------------------------------------------------------
__global__ void softmax_kernel(float* __restrict__ S, int rowStride,
                               int Npad, int Nvalid, float scale)
{
    int row = blockIdx.x, head = blockIdx.y, t = threadIdx.x;
    float* p = S + ((size_t)head * rowStride + row) * Npad;
    __shared__ float srow[LX];
    __shared__ float red[256];

    float mx = -1e30f;
    for (int j = t; j < Nvalid; j += 256) {
        float v = p[j] * scale;
        srow[j] = v;
        mx = fmaxf(mx, v);
    }
    red[t] = mx; __syncthreads();
    for (int st = 128; st > 0; st >>= 1) { if (t < st) red[t] = fmaxf(red[t], red[t + st]); __syncthreads(); }
    mx = red[0];
    __syncthreads();

    float sum = 0.f;
    for (int j = t; j < Nvalid; j += 256) {
        float e = __expf(srow[j] - mx);
        srow[j] = e;
        sum += e;
    }
    red[t] = sum; __syncthreads();
    for (int st = 128; st > 0; st >>= 1) { if (t < st) red[t] += red[t + st]; __syncthreads(); }
    float inv = 1.f / red[0];

    for (int j = t; j < Nvalid; j += 256) p[j] = srow[j] * inv;
    for (int j = Nvalid + t; j < Npad; j += 256) p[j] = 0.f;
}

// ---------------------------------------------------------------------------
// cat[l][0:1536] = attn (from head-major O), cat[l][1536:] = gelu(mlp)
// ---------------------------------------------------------------------------
__global__ void cat_kernel(const float* __restrict__ O, int OL,
                           const float* __restrict__ mlp, int ldm,
                           float* __restrict__ cat)
{
    int l = blockIdx.y;
    int c = blockIdx.x * 256 + threadIdx.x;
    float v;
    if (c < HID) {
        int hd = c >> 7, d = c & 127;
        v = O[((size_t)hd * OL + l) * HD + d];
    } else {
        float xg = mlp[(size_t)l * ldm + (c - HID)];
        float u = 0.7978845608028654f * (xg + 0.044715f * xg * xg * xg);
        v = 0.5f * xg * (1.f + tanhf(u));
    }
    cat[(size_t)l * CATW + c] = v;
}

// ---------------------------------------------------------------------------
// kernel_launch
// ---------------------------------------------------------------------------
#define SMEM_FOR(BN, S) (1024 + (S) * ((128 * 128) + (BN) * 128))

extern "C" void kernel_launch(void* const* d_in, const int* in_sizes, int n_in,
                              void* d_out, int out_size)
{
    (void)in_sizes; (void)n_in; (void)out_size;
    const float* x   = (const float*)d_in[0];
    const float* cps = (const float*)d_in[1];
    const float* vec = (const float*)d_in[2];
    const float* pe  = (const float*)d_in[3];
    const float* cpe = (const float*)d_in[4];
    const float* w1  = (const float*)d_in[5];
    const float* b1  = (const float*)d_in[6];
    const float* w2  = (const float*)d_in[7];
    const float* b2  = (const float*)d_in[8];
    const float* qs  = (const float*)d_in[9];
    const float* ks  = (const float*)d_in[10];
    const float* mw  = (const float*)d_in[11];
    const float* mb  = (const float*)d_in[12];
    float* out = (float*)d_out;

    const int SM256 = SMEM_FOR(256, 4);
    const int SM128 = SMEM_FOR(128, 6);
    cudaFuncSetAttribute(tc_gemm<256, 4, 0>, cudaFuncAttributeMaxDynamicSharedMemorySize, SM256);
    cudaFuncSetAttribute(tc_gemm<256, 4, 1>, cudaFuncAttributeMaxDynamicSharedMemorySize, SM256);
    cudaFuncSetAttribute(tc_gemm<128, 6, 0>, cudaFuncAttributeMaxDynamicSharedMemorySize, SM128);

    float *m, *xm, *h, *h2kv, *h2f, *q, *k, *v, *q2, *k2, *v2, *S, *S2, *O, *O2, *cat, *cat2;
    cudaGetSymbolAddress((void**)&m,    g_m);
    cudaGetSymbolAddress((void**)&xm,   g_xm);
    cudaGetSymbolAddress((void**)&h,    g_h);
    cudaGetSymbolAddress((void**)&h2kv, g_h2kv);
    cudaGetSymbolAddress((void**)&h2f,  g_h2f);
    cudaGetSymbolAddress((void**)&q,    g_q);
    cudaGetSymbolAddress((void**)&k,    g_k);
    cudaGetSymbolAddress((void**)&v,    g_v);
    cudaGetSymbolAddress((void**)&q2,   g_q2);
    cudaGetSymbolAddress((void**)&k2,   g_k2);
    cudaGetSymbolAddress((void**)&v2,   g_v2);
    cudaGetSymbolAddress((void**)&S,    g_S);
    cudaGetSymbolAddress((void**)&S2,   g_S2);
    cudaGetSymbolAddress((void**)&O,    g_O);
    cudaGetSymbolAddress((void**)&O2,   g_O2);
    cudaGetSymbolAddress((void**)&cat,  g_cat);
    cudaGetSymbolAddress((void**)&cat2, g_cat2);

    mod_kernel<<<3 * HID, 256>>>(vec, mw, mb, m);

    // ================= Block 1 (L = 4352) =================
    ln_mod_kernel<<<LX, 256>>>(x, xm, m);

    // h = xm @ w1.T + b1
    tc_gemm<256, 4, 0><<<dim3(W1ROWS / 256, LX / 128, 1), 256, SM256>>>(
        xm, w1, h, HID, HID, HID, W1ROWS, 0, 0, 0, b1, nullptr, 0, nullptr, LX);

    dim3 gqk(LX, NH);
    rmsrope_kernel<<<gqk, HD>>>(h + 0,       W1ROWS, pe, qs,      1, q, LX, 0);
    rmsrope_kernel<<<gqk, HD>>>(h + HID,     W1ROWS, pe, ks,      1, k, LX, 0);
    rmsrope_kernel<<<gqk, HD>>>(h + 2 * HID, W1ROWS, pe, nullptr, 0, v, LX, 1);  // vT

    // S = q @ k^T
    tc_gemm<256, 4, 0><<<dim3(LX / 256, LX / 128, NH), 256, SM256>>>(
        q, k, S, HD, HD, HD, LX,
        (size_t)LX * HD, (size_t)LX * HD, (size_t)LX * LX,
        nullptr, nullptr, 0, nullptr, LX);

    softmax_kernel<<<dim3(LX, NH), 256>>>(S, LX, LX, LX, SOFT_SCALE);

    // O = P @ V   (B = vT, NT)
    tc_gemm<128, 6, 0><<<dim3(1, LX / 128, NH), 256, SM128>>>(
        S, v, O, LX, LX, LX, HD,
        (size_t)LX * LX, (size_t)HD * LX, (size_t)LX * HD,
        nullptr, nullptr, 0, nullptr, LX);

    cat_kernel<<<dim3(CATW / 256, LX), 256>>>(O, LX, h + 3 * HID, W1ROWS, cat);

    // out_x = x + gate * (cat @ w2.T + b2)
    tc_gemm<256, 4, 1><<<dim3(HID / 256, LX / 128, 1), 256, SM256>>>(
        cat, w2, out, CATW, CATW, CATW, HID, 0, 0, 0, b2, x, HID, m + 2 * HID, LX);

    // ================= Block 2 (L = 4116, only 20 output rows kept) =========
    ln_mod_kernel<<<NC, 256>>>(cps, xm, m);
    ln_mod_kernel<<<4096, 256>>>(x + (size_t)256 * HID, xm + (size_t)NC * HID, m);

    // k,v for all rows (w1 cols 1536..4607); padded M rows read stale xm (deterministic)
    tc_gemm<256, 4, 0><<<dim3(3072 / 256, L2P / 128, 1), 256, SM256>>>(
        xm, w1 + (size_t)HID * HID, h2kv, HID, HID, HID, 3072,
        0, 0, 0, b1 + HID, nullptr, 0, nullptr, L2P);

    // full h (q + mlp) for first 128 rows (only 20 used)
    tc_gemm<256, 4, 0><<<dim3(W1ROWS / 256, 1, 1), 256, SM256>>>(
        xm, w1, h2f, HID, HID, HID, W1ROWS, 0, 0, 0, b1, nullptr, 0, nullptr, 128);

    dim3 gk2(L2V, NH);
    rmsrope_kernel<<<gk2, HD>>>(h2kv + 0,   3072, cpe, ks,      1, k2, L2P, 0);
    rmsrope_kernel<<<gk2, HD>>>(h2kv + HID, 3072, cpe, nullptr, 0, v2, L2P, 1);  // vT
    rmsrope_kernel<<<dim3(NC, NH), HD>>>(h2f + 0, W1ROWS, cpe, qs, 1, q2, 128, 0);

    tc_gemm<256, 4, 0><<<dim3(L2P / 256, 1, NH), 256, SM256>>>(
        q2, k2, S2, HD, HD, HD, L2P,
        (size_t)128 * HD, (size_t)L2P * HD, (size_t)128 * L2P,
        nullptr, nullptr, 0, nullptr, 128);

    softmax_kernel<<<dim3(NC, NH), 256>>>(S2, 128, L2P, L2V, SOFT_SCALE);

    tc_gemm<128, 6, 0><<<dim3(1, 1, NH), 256, SM128>>>(
        S2, v2, O2, L2P, L2P, L2P, HD,
        (size_t)128 * L2P, (size_t)HD * L2P, (size_t)128 * HD,
        nullptr, nullptr, 0, nullptr, 128);

    cat_kernel<<<dim3(CATW / 256, NC), 256>>>(O2, 128, h2f + 3 * HID, W1ROWS, cat2);

    // concepts_out = concepts + gate * (cat2 @ w2.T + b2)   (store 20 rows only)
    tc_gemm<256, 4, 1><<<dim3(HID / 256, 1, 1), 256, SM256>>>(
        cat2, w2, out + (size_t)LX * HID, CATW, CATW, CATW, HID,
        0, 0, 0, b2, cps, HID, m + 2 * HID, NC);
}

// round 8
// speedup vs baseline: 8.4108x; 1.4659x over previous
#include <cuda_runtime.h>
#include <cuda_bf16.h>
#include <cstdint>
#include <cstddef>

#define HID     1536
#define NH      12
#define HD      128
#define MLP     6144
#define LX      4352
#define NC      20
#define L2V     4116
#define L2P     4352
#define QKVW    4608
#define CATW    7680
#define NSPLIT  4
#define SOFT_SCALE 0.08838834764831845f

typedef unsigned int u32;
typedef unsigned long long u64;

#if defined(__CUDA_ARCH_FEAT_SM103_ALL) || defined(__CUDA_ARCH_FEAT_SM100_ALL) || defined(__CUDA_ARCH_FEAT_SM101_ALL)
#define HAS_TCGEN05 1
#else
#define HAS_TCGEN05 0
#endif

// ---------------- scratch ----------------
__device__ __align__(256) float g_m[3 * HID];
__device__ __align__(256) float g_xm[(size_t)LX * HID];
__device__ __align__(256) float g_h[(size_t)LX * QKVW];
__device__ __align__(256) float g_h2kv[(size_t)L2P * 3072];
__device__ __align__(256) float g_h2f[(size_t)128 * HID];
__device__ __align__(256) float g_q[(size_t)NH * LX * HD];
__device__ __align__(256) float g_k[(size_t)NH * LX * HD];
__device__ __align__(256) float g_v[(size_t)NH * HD * LX];      // vT [h][d][l]
__device__ __align__(256) float g_q2[(size_t)NH * 128 * HD];
__device__ __align__(256) float g_k2[(size_t)NH * L2P * HD];
__device__ __align__(256) float g_v2[(size_t)NH * HD * L2P];
__device__ __align__(256) float g_cat[(size_t)LX * CATW];
__device__ __align__(256) float g_cat2[(size_t)128 * CATW];
__device__ __align__(256) float g_O2p[(size_t)NSPLIT * NH * 128 * HD];
__device__ __align__(256) float g_l2[(size_t)NSPLIT * NH * 128];

// ---------------- PTX helpers ----------------
__device__ __forceinline__ u32 s2u(const void* p) { return (u32)__cvta_generic_to_shared(p); }
__device__ __forceinline__ u32 swz(u32 o) { return o ^ ((o >> 3) & 0x70); }
__device__ __forceinline__ void cp16(u32 dst, const void* src) {
    asm volatile("cp.async.cg.shared.global [%0], [%1], 16;" :: "r"(dst), "l"(src));
}
__device__ __forceinline__ void cp_commit() { asm volatile("cp.async.commit_group;" ::: "memory"); }
template <int N> __device__ __forceinline__ void cp_wait() {
    asm volatile("cp.async.wait_group %0;" :: "n"(N) : "memory");
}
__device__ __forceinline__ bool elect1() {
    u32 p;
    asm volatile("{\n\t.reg .pred p;\n\telect.sync _|p, 0xFFFFFFFF;\n\tselp.b32 %0,1,0,p;\n\t}" : "=r"(p));
    return p != 0;
}
__device__ __forceinline__ u64 sdesc(u32 addr) {
    return 0x4000404000010000ull | (u64)((addr >> 4) & 0x3FFF);
}
__device__ __forceinline__ void mbar_init(u32 a) {
    u32 one = 1;
    asm volatile("mbarrier.init.shared.b64 [%0], %1;" :: "r"(a), "r"(one) : "memory");
}
__device__ __forceinline__ void mbar_wait(u32 a, u32 parity) {
    asm volatile(
        "{\n\t.reg .pred P;\n"
        "LW_%=:\n\t"
        "mbarrier.try_wait.parity.acquire.cta.shared::cta.b64 P, [%0], %1, 0x989680;\n\t"
        "@P bra LD_%=;\n\t"
        "bra LW_%=;\n"
        "LD_%=:\n\t}" :: "r"(a), "r"(parity) : "memory");
}
__device__ __forceinline__ void fence_async_shared() {
    asm volatile("fence.proxy.async.shared::cta;" ::: "memory");
}
__device__ __forceinline__ void tc_commit(u32 mbar) {
#if HAS_TCGEN05
    asm volatile("tcgen05.commit.cta_group::1.mbarrier::arrive::one.shared::cluster.b64 [%0];"
                 :: "r"(mbar) : "memory");
#else
    (void)mbar;
#endif
}
__device__ __forceinline__ void mma_tf32(u32 d, u64 ad, u64 bd, u32 idesc, u32 en) {
#if HAS_TCGEN05
    asm volatile(
        "{\n\t.reg .pred p;\n\tsetp.ne.u32 p, %4, 0;\n\t"
        "tcgen05.mma.cta_group::1.kind::tf32 [%0], %1, %2, %3, {%5,%5,%5,%5}, p;\n\t}"
        :: "r"(d), "l"(ad), "l"(bd), "r"(idesc), "r"(en), "r"(0u) : "memory");
#else
    (void)d; (void)ad; (void)bd; (void)idesc; (void)en;
#endif
}
__device__ __forceinline__ void tc_fence_after() {
#if HAS_TCGEN05
    asm volatile("tcgen05.fence::after_thread_sync;" ::: "memory");
#endif
}
__device__ __forceinline__ void tc_fence_before() {
#if HAS_TCGEN05
    asm volatile("tcgen05.fence::before_thread_sync;" ::: "memory");
#endif
}
__device__ __forceinline__ void tmem_alloc(u32 dst_smem, u32 ncols) {
#if HAS_TCGEN05
    asm volatile("tcgen05.alloc.cta_group::1.sync.aligned.shared::cta.b32 [%0], %1;"
                 :: "r"(dst_smem), "r"(ncols) : "memory");
#else
    (void)dst_smem; (void)ncols;
#endif
}
__device__ __forceinline__ void tmem_relinquish() {
#if HAS_TCGEN05
    asm volatile("tcgen05.relinquish_alloc_permit.cta_group::1.sync.aligned;");
#endif
}
__device__ __forceinline__ void tmem_dealloc(u32 tmem, u32 ncols) {
#if HAS_TCGEN05
    asm volatile("tcgen05.dealloc.cta_group::1.sync.aligned.b32 %0, %1;" :: "r"(tmem), "r"(ncols));
#else
    (void)tmem; (void)ncols;
#endif
}
__device__ __forceinline__ void tmem_wait_ld() {
#if HAS_TCGEN05
    asm volatile("tcgen05.wait::ld.sync.aligned;" ::: "memory");
#endif
}
__device__ __forceinline__ void ldtm32(u32* r, u32 a) {
#if HAS_TCGEN05
    asm volatile(
        "tcgen05.ld.sync.aligned.32x32b.x32.b32 "
        "{%0, %1, %2, %3, %4, %5, %6, %7, "
        " %8, %9, %10, %11, %12, %13, %14, %15, "
        " %16, %17, %18, %19, %20, %21, %22, %23, "
        " %24, %25, %26, %27, %28, %29, %30, %31}, [%32];"
        : "=r"(r[0]),  "=r"(r[1]),  "=r"(r[2]),  "=r"(r[3]),
          "=r"(r[4]),  "=r"(r[5]),  "=r"(r[6]),  "=r"(r[7]),
          "=r"(r[8]),  "=r"(r[9]),  "=r"(r[10]), "=r"(r[11]),
          "=r"(r[12]), "=r"(r[13]), "=r"(r[14]), "=r"(r[15]),
          "=r"(r[16]), "=r"(r[17]), "=r"(r[18]), "=r"(r[19]),
          "=r"(r[20]), "=r"(r[21]), "=r"(r[22]), "=r"(r[23]),
          "=r"(r[24]), "=r"(r[25]), "=r"(r[26]), "=r"(r[27]),
          "=r"(r[28]), "=r"(r[29]), "=r"(r[30]), "=r"(r[31])
        : "r"(a));
#else
#pragma unroll
    for (int i = 0; i < 32; ++i) r[i] = 0u;
    (void)a;
#endif
}
__device__ __forceinline__ float gelu_f(float x) {
    float u = 0.7978845608028654f * (x + 0.044715f * x * x * x);
    return 0.5f * x * (1.f + tanhf(u));
}

// ---------------- generic tf32 GEMM (NT) ----------------
template <int BN>
__device__ __forceinline__ void load_chunk(u32 st, const float* A, const float* B,
                                           int bm, int bn, int kt, int lda, int ldb, int tid)
{
#pragma unroll
    for (int i = 0; i < 4; ++i) {
        int o = tid + (i << 8);
        int r = o >> 3, c = o & 7;
        cp16(st + swz((u32)((r << 7) + (c << 4))),
             A + (size_t)(bm + r) * lda + kt + (c << 2));
    }
    const u32 stB = st + 128 * 128;
#pragma unroll
    for (int i = 0; i < BN / 32; ++i) {
        int o = tid + (i << 8);
        int r = o >> 3, c = o & 7;
        cp16(stB + swz((u32)((r << 7) + (c << 4))),
             B + (size_t)(bn + r) * ldb + kt + (c << 2));
    }
}

// EPI 0: +bias. 1: res + gate*(acc+bias). 2: gelu(acc+bias).
template <int BN, int STAGES, int EPI>
__global__ __launch_bounds__(256, 1)
void tc_gemm(const float* __restrict__ A, const float* __restrict__ B, float* __restrict__ C,
             int K, int lda, int ldb, int ldc,
             size_t sA, size_t sB, size_t sC,
             const float* __restrict__ bias,
             const float* __restrict__ res, int ldres,
             const float* __restrict__ gate, int Mstore)
{
    constexpr int ASZ = 128 * 128;
    constexpr int STRIDE = ASZ + BN * 128;
    constexpr u32 IDESC = (1u << 4) | (2u << 7) | (2u << 10) |
                          ((u32)(BN / 8) << 17) | (8u << 24);

    extern __shared__ char smem[];
    const u32 sb = s2u(smem);
    const u32 mb0 = sb + 8;
    const u32 tile0 = sb + 1024;

    A += (size_t)blockIdx.z * sA;
    B += (size_t)blockIdx.z * sB;
    C += (size_t)blockIdx.z * sC;
    const int bm = blockIdx.y * 128;
    const int bn = blockIdx.x * BN;
    const int tid = threadIdx.x;

    if (tid == 0)
        for (int s = 0; s < STAGES; ++s) mbar_init(mb0 + 8 * s);
    if (tid < 32) { tmem_alloc(sb, BN); tmem_relinquish(); }
    __syncthreads();
    u32 tmem;
    asm volatile("ld.shared.b32 %0, [%1];" : "=r"(tmem) : "r"(sb));

    const int nk = K >> 5;
    for (int p = 0; p < STAGES - 1; ++p) {
        if (p < nk)
            load_chunk<BN>(tile0 + (p % STAGES) * STRIDE, A, B, bm, bn, p << 5, lda, ldb, tid);
        cp_commit();
    }

    for (int it = 0; it < nk; ++it) {
        const int b = it % STAGES;
        cp_wait<STAGES - 2>();
        fence_async_shared();
        __syncthreads();

        if (tid < 32) {
            u64 da = sdesc(tile0 + b * STRIDE);
            u64 db = sdesc(tile0 + b * STRIDE + ASZ);
            if (elect1()) {
#pragma unroll
                for (int j = 0; j < 4; ++j)
                    mma_tf32(tmem, da + j * 2, db + j * 2, IDESC, (u32)((it > 0) || (j > 0)));
                tc_commit(mb0 + 8 * b);
            }
        }
        const int p = it + STAGES - 1;
        if (p < nk) {
            if (it >= 1)
                mbar_wait(mb0 + 8 * (p % STAGES), (u32)(((it - 1) / STAGES) & 1));
            load_chunk<BN>(tile0 + (p % STAGES) * STRIDE, A, B, bm, bn, p << 5, lda, ldb, tid);
        }
        cp_commit();
    }

    mbar_wait(mb0 + 8 * ((nk - 1) % STAGES), (u32)(((nk - 1) / STAGES) & 1));
    tc_fence_after();

    if (tid < 128) {
        const int w = tid >> 5, lane = tid & 31;
        const int row = bm + w * 32 + lane;
        const bool doSt = row < Mstore;
        float* crow = C + (size_t)row * ldc;
        const float* rrow = (EPI == 1 && doSt) ? (res + (size_t)row * ldres) : nullptr;
#pragma unroll
        for (int g = 0; g < BN / 32; ++g) {
            u32 regs[32];
            ldtm32(regs, tmem + g * 32);
            tmem_wait_ld();
            if (doSt) {
#pragma unroll
                for (int q4 = 0; q4 < 8; ++q4) {
                    int col = bn + g * 32 + q4 * 4;
                    float4 vv;
                    vv.x = __uint_as_float(regs[q4 * 4 + 0]);
                    vv.y = __uint_as_float(regs[q4 * 4 + 1]);
                    vv.z = __uint_as_float(regs[q4 * 4 + 2]);
                    vv.w = __uint_as_float(regs[q4 * 4 + 3]);
                    if (bias) {
                        float4 bb = *(const float4*)(bias + col);
                        vv.x += bb.x; vv.y += bb.y; vv.z += bb.z; vv.w += bb.w;
                    }
                    if (EPI == 1) {
                        float4 rr = *(const float4*)(rrow + col);
                        float4 gg = *(const float4*)(gate + col);
                        vv.x = rr.x + gg.x * vv.x; vv.y = rr.y + gg.y * vv.y;
                        vv.z = rr.z + gg.z * vv.z; vv.w = rr.w + gg.w * vv.w;
                    } else if (EPI == 2) {
                        vv.x = gelu_f(vv.x); vv.y = gelu_f(vv.y);
                        vv.z = gelu_f(vv.z); vv.w = gelu_f(vv.w);
                    }
                    *(float4*)(crow + col) = vv;
                }
            }
        }
    }
    __syncthreads();
    if (tid < 32) tmem_dealloc(tmem, BN);
}

// ---------------- flash attention ----------------
__device__ __forceinline__ void ld_ktile(u32 dstb, const float* Kb, int jt, int tid) {
#pragma unroll
    for (int i = 0; i < 8; ++i) {
        int o = tid + (i << 8);
        int row = o >> 5, inner = o & 31, c = inner >> 3, s = inner & 7;
        cp16(dstb + c * 8192 + swz((u32)((row << 7) + (s << 4))),
             Kb + (size_t)(jt * 64 + row) * HD + (c << 5) + (s << 2));
    }
}
__device__ __forceinline__ void ld_vtile(u32 dstb, const float* Vb, int jt, int vLD, int tid) {
#pragma unroll
    for (int i = 0; i < 8; ++i) {
        int o = tid + (i << 8);
        int row = o >> 4, inner = o & 15, c = inner >> 3, s = inner & 7;
        cp16(dstb + c * 16384 + swz((u32)((row << 7) + (s << 4))),
             Vb + (size_t)row * vLD + jt * 64 + (c << 5) + (s << 2));
    }
}
#define IDESC_QK ((1u << 4) | (2u << 7) | (2u << 10) | (8u << 17) | (8u << 24))
#define IDESC_PV ((1u << 4) | (2u << 7) | (2u << 10) | (16u << 17) | (8u << 24))

__device__ __forceinline__ void issue_qk(u32 dcol, u32 sQ, u32 sKb) {
#pragma unroll
    for (int c = 0; c < 4; ++c) {
        u64 da = sdesc(sQ + c * 16384);
        u64 db = sdesc(sKb + c * 8192);
#pragma unroll
        for (int j = 0; j < 4; ++j)
            mma_tf32(dcol, da + j * 2, db + j * 2, IDESC_QK, (u32)((c | j) != 0));
    }
}
__device__ __forceinline__ void issue_pv(u32 dcol, u32 sPb, u32 sVb, bool first) {
#pragma unroll
    for (int c = 0; c < 2; ++c) {
        u64 da = sdesc(sPb + c * 16384);
        u64 db = sdesc(sVb + c * 16384);
#pragma unroll
        for (int j = 0; j < 4; ++j)
            mma_tf32(dcol, da + j * 2, db + j * 2, IDESC_PV,
                     (u32)(!(first && c == 0 && j == 0)));
    }
}

#define FL_SMEM (2048 + 65536 + 65536 + 65536 + 32768)

// SPLITOUT=0: dst[bm+r][ldd] gets O/l directly at col h*HD. grid (M/128, NH).
// SPLITOUT=1: grid (NSPLIT, NH); raw partials O + l.
template <int SPLITOUT>
__global__ __launch_bounds__(256, 1)
void flash_kernel(const float* __restrict__ Qg, const float* __restrict__ Kg,
                  const float* __restrict__ Vg,
                  float* __restrict__ dst, float* __restrict__ lout,
                  size_t qHS, size_t kHS, size_t vHS, int vLD,
                  int nt, int nvalid, int ldd)
{
    extern __shared__ char smem[];
    float* rowsum = (float*)(smem + 16);
    const u32 sb = s2u(smem);
    const u32 mbar = sb + 8;
    const u32 sQ = sb + 2048;
    const u32 sK = sQ + 65536;
    const u32 sV = sK + 65536;
    const u32 sP = sV + 65536;

    const int h = blockIdx.y;
    const int tid = threadIdx.x;
    const int wid = tid >> 5, lane = tid & 31;
    const int hf = wid >> 2;
    const int r = ((wid & 3) << 5) + lane;
    const int t0 = SPLITOUT ? blockIdx.x * nt : 0;
    const int bm = SPLITOUT ? 0 : blockIdx.x * 128;

    const float* Qb = Qg + (size_t)h * qHS + (size_t)bm * HD;
    const float* Kb = Kg + (size_t)h * kHS;
    const float* Vb = Vg + (size_t)h * vHS;

#pragma unroll
    for (int i = 0; i < 16; ++i) {          // Q resident
        int o = tid + (i << 8);
        int row = o >> 5, inner = o & 31, c = inner >> 3, s = inner & 7;
        cp16(sQ + c * 16384 + swz((u32)((row << 7) + (s << 4))),
             Qb + (size_t)row * HD + (c << 5) + (s << 2));
    }
    ld_ktile(sK, Kb, t0, tid);
    ld_vtile(sV, Vb, t0, vLD, tid);
    cp_commit();                            // group: Q,K0,V0
    if (nt > 1) ld_ktile(sK + 32768, Kb, t0 + 1, tid);
    cp_commit();                            // group: K1

    if (tid == 0) mbar_init(mbar);
    if (tid < 32) { tmem_alloc(sb, 256); tmem_relinquish(); }
    __syncthreads();
    u32 tmem;
    asm volatile("ld.shared.b32 %0, [%1];" : "=r"(tmem) : "r"(sb));
    const u32 tO = tmem;                    // O cols 0..127; S bufs at +128,+192

    cp_wait<1>();
    fence_async_shared();
    __syncthreads();
    if (tid < 32 && elect1()) {
        issue_qk(tmem + 128, sQ, sK);
        tc_commit(mbar);
    }

    float lacc = 0.f;
    u32 par = 0;

    for (int t = 0; t < nt; ++t) {
        const u32 scol = 128 + ((u32)(t & 1) << 6);

        mbar_wait(mbar, par); par ^= 1;     // QK[t] (and PV[t-1]) complete
        tc_fence_after();
        cp_wait<0>();                       // K[t+1], V[t] resident
        fence_async_shared();
        __syncthreads();

        if (tid < 32 && elect1()) {
            if (t + 1 < nt)
                issue_qk(tmem + 128 + ((u32)((t + 1) & 1) << 6),
                         sQ, sK + ((u32)((t + 1) & 1) * 32768u));
        }
        if (t + 2 < nt) ld_ktile(sK + ((u32)(t & 1) * 32768u), Kb, t0 + t + 2, tid);
        if (t + 1 < nt) ld_vtile(sV + ((u32)((t + 1) & 1) * 32768u), Vb, t0 + t + 1, vLD, tid);
        cp_commit();

        // softmax (no max subtraction; logits bounded)
        u32 sr[32];
        ldtm32(sr, tmem + scol + ((u32)hf << 5));
        tmem_wait_ld();
        float p[32];
        float ls = 0.f;
        const int jb = (t0 + t) * 64 + (hf << 5);
#pragma unroll
        for (int i = 0; i < 32; ++i) {
            float sv = __uint_as_float(sr[i]);
            float e = (jb + i < nvalid) ? __expf(sv) : 0.f;
            p[i] = e; ls += e;
        }
        lacc += ls;

        const u32 pbase = sP + (hf ? 16384u : 0u);
#pragma unroll
        for (int g = 0; g < 8; ++g) {
            u32 addr = pbase + swz(((u32)r << 7) + ((u32)g << 4));
            asm volatile("st.shared.v4.b32 [%0], {%1,%2,%3,%4};" :: "r"(addr),
                "r"(__float_as_uint(p[4 * g + 0])), "r"(__float_as_uint(p[4 * g + 1])),
                "r"(__float_as_uint(p[4 * g + 2])), "r"(__float_as_uint(p[4 * g + 3]))
                : "memory");
        }
        tc_fence_before();
        fence_async_shared();
        __syncthreads();

        if (tid < 32 && elect1()) {
            tc_fence_after();
            issue_pv(tO, sP, sV + ((u32)(t & 1) * 32768u), t == 0);
            tc_commit(mbar);
        }
    }

    mbar_wait(mbar, par);                   // final PV complete
    tc_fence_after();

    rowsum[r * 2 + hf] = lacc;
    __syncthreads();
    const float ltot = rowsum[r * 2] + rowsum[r * 2 + 1];

    if (SPLITOUT) {
        float* od = dst + (((size_t)blockIdx.x * NH + h) * 128 + r) * HD + (hf << 6);
#pragma unroll
        for (int g2 = 0; g2 < 2; ++g2) {
            u32 orgs[32];
            ldtm32(orgs, tO + ((u32)hf << 6) + ((u32)g2 << 5));
            tmem_wait_ld();
#pragma unroll
            for (int i = 0; i < 8; ++i) {
                float4 vv;
                vv.x = __uint_as_float(orgs[i * 4 + 0]);
                vv.y = __uint_as_float(orgs[i * 4 + 1]);
                vv.z = __uint_as_float(orgs[i * 4 + 2]);
                vv.w = __uint_as_float(orgs[i * 4 + 3]);
                *(float4*)(od + (g2 << 5) + i * 4) = vv;
            }
        }
        if (hf == 0)
            lout[((size_t)blockIdx.x * NH + h) * 128 + r] = ltot;
    } else {
        const float inv = 1.f / ltot;
        float* od = dst + (size_t)(bm + r) * ldd + h * HD + (hf << 6);
#pragma unroll
        for (int g2 = 0; g2 < 2; ++g2) {
            u32 orgs[32];
            ldtm32(orgs, tO + ((u32)hf << 6) + ((u32)g2 << 5));
            tmem_wait_ld();
#pragma unroll
            for (int i = 0; i < 8; ++i) {
                float4 vv;
                vv.x = __uint_as_float(orgs[i * 4 + 0]) * inv;
                vv.y = __uint_as_float(orgs[i * 4 + 1]) * inv;
                vv.z = __uint_as_float(orgs[i * 4 + 2]) * inv;
                vv.w = __uint_as_float(orgs[i * 4 + 3]) * inv;
                *(float4*)(od + (g2 << 5) + i * 4) = vv;
            }
        }
    }
    tc_fence_before();
    __syncthreads();
    if (tid < 32) tmem_dealloc(tmem, 256);
}

// combine split-K partials into cat2 attn columns
__global__ void combine2_kernel(const float* __restrict__ Op, const float* __restrict__ lp,
                                float* __restrict__ cat2)
{
    int r = blockIdx.x, h = blockIdx.y, d = threadIdx.x;
    float o = 0.f, l = 0.f;
#pragma unroll
    for (int s = 0; s < NSPLIT; ++s) {
        o += Op[(((size_t)s * NH + h) * 128 + r) * HD + d];
        l += lp[((size_t)s * NH + h) * 128 + r];
    }
    cat2[(size_t)r * CATW + h * HD + d] = o / l;
}

// ---------------- small elementwise kernels ----------------
__global__ void mod_kernel(const float* __restrict__ vec, const float* __restrict__ mw,
                           const float* __restrict__ mb, float* __restrict__ m)
{
    int o = blockIdx.x, t = threadIdx.x;
    float s = 0.f;
    for (int k = t; k < HID; k += 256) {
        float v = vec[k];
        s += (v / (1.f + expf(-v))) * mw[(size_t)o * HID + k];
    }
    __shared__ float red[256];
    red[t] = s; __syncthreads();
    for (int st = 128; st > 0; st >>= 1) { if (t < st) red[t] += red[t + st]; __syncthreads(); }
    if (t == 0) m[o] = red[0] + mb[o];
}

__global__ void ln_mod_kernel(const float* __restrict__ in, float* __restrict__ out,
                              const float* __restrict__ m)
{
    int row = blockIdx.x, t = threadIdx.x;
    const float* x = in + (size_t)row * HID;
    __shared__ float buf[HID];
    __shared__ float red[256];

    float s = 0.f;
    for (int c = t; c < HID; c += 256) { float v = x[c]; buf[c] = v; s += v; }
    red[t] = s; __syncthreads();
    for (int st = 128; st > 0; st >>= 1) { if (t < st) red[t] += red[t + st]; __syncthreads(); }
    float mu = red[0] * (1.f / HID);
    __syncthreads();

    float ss = 0.f;
    for (int c = t; c < HID; c += 256) { float d = buf[c] - mu; ss += d * d; }
    red[t] = ss; __syncthreads();
    for (int st = 128; st > 0; st >>= 1) { if (t < st) red[t] += red[t + st]; __syncthreads(); }
    float inv = rsqrtf(red[0] * (1.f / HID) + 1e-6f);

    float* o = out + (size_t)row * HID;
    for (int c = t; c < HID; c += 256)
        o[c] = (1.f + m[HID + c]) * ((buf[c] - mu) * inv) + m[c];
}

__global__ void rmsrope_kernel(const float* __restrict__ src, int ldh,
                               const float* __restrict__ pe,
                               const float* __restrict__ scale, int dorope,
                               float* __restrict__ dst, int dstL, int transp,
                               float premul)
{
    int l = blockIdx.x, hd = blockIdx.y, d = threadIdx.x;
    float v = src[(size_t)l * ldh + hd * HD + d];
    __shared__ float sv[HD];
    __shared__ float wred[4];

    if (scale) {
        float ss = v * v;
#pragma unroll
        for (int o = 16; o > 0; o >>= 1) ss += __shfl_xor_sync(0xffffffffu, ss, o);
        if ((d & 31) == 0) wred[d >> 5] = ss;
        __syncthreads();
        float tot = wred[0] + wred[1] + wred[2] + wred[3];
        v = v * rsqrtf(tot * (1.f / HD) + 1e-6f) * scale[d] * premul;
        __syncthreads();
    }
    float outv;
    if (dorope) {
        sv[d] = v; __syncthreads();
        int i = d >> 1, j = d & 1;
        const float* pp = pe + (size_t)l * 256 + i * 4 + j * 2;
        outv = pp[0] * sv[2 * i] + pp[1] * sv[2 * i + 1];
    } else {
        outv = v;
    }
    if (transp)
        dst[((size_t)hd * HD + d) * dstL + l] = outv;
    else
        dst[((size_t)hd * dstL + l) * HD + d] = outv;
}

// ---------------- launch ----------------
#define SMEM_FOR(BN, S) (1024 + (S) * ((128 * 128) + (BN) * 128))

extern "C" void kernel_launch(void* const* d_in, const int* in_sizes, int n_in,
                              void* d_out, int out_size)
{
    (void)in_sizes; (void)n_in; (void)out_size;
    const float* x   = (const float*)d_in[0];
    const float* cps = (const float*)d_in[1];
    const float* vec = (const float*)d_in[2];
    const float* pe  = (const float*)d_in[3];
    const float* cpe = (const float*)d_in[4];
    const float* w1  = (const float*)d_in[5];
    const float* b1  = (const float*)d_in[6];
    const float* w2  = (const float*)d_in[7];
    const float* b2  = (const float*)d_in[8];
    const float* qs  = (const float*)d_in[9];
    const float* ks  = (const float*)d_in[10];
    const float* mw  = (const float*)d_in[11];
    const float* mb  = (const float*)d_in[12];
    float* out = (float*)d_out;

    const int SM256 = SMEM_FOR(256, 4);
    cudaFuncSetAttribute(tc_gemm<256, 4, 0>, cudaFuncAttributeMaxDynamicSharedMemorySize, SM256);
    cudaFuncSetAttribute(tc_gemm<256, 4, 1>, cudaFuncAttributeMaxDynamicSharedMemorySize, SM256);
    cudaFuncSetAttribute(tc_gemm<256, 4, 2>, cudaFuncAttributeMaxDynamicSharedMemorySize, SM256);
    cudaFuncSetAttribute(flash_kernel<0>, cudaFuncAttributeMaxDynamicSharedMemorySize, FL_SMEM);
    cudaFuncSetAttribute(flash_kernel<1>, cudaFuncAttributeMaxDynamicSharedMemorySize, FL_SMEM);

    float *m, *xm, *h, *h2kv, *h2f, *q, *k, *v, *q2, *k2, *v2, *cat, *cat2, *O2p, *l2;
    cudaGetSymbolAddress((void**)&m,    g_m);
    cudaGetSymbolAddress((void**)&xm,   g_xm);
    cudaGetSymbolAddress((void**)&h,    g_h);
    cudaGetSymbolAddress((void**)&h2kv, g_h2kv);
    cudaGetSymbolAddress((void**)&h2f,  g_h2f);
    cudaGetSymbolAddress((void**)&q,    g_q);
    cudaGetSymbolAddress((void**)&k,    g_k);
    cudaGetSymbolAddress((void**)&v,    g_v);
    cudaGetSymbolAddress((void**)&q2,   g_q2);
    cudaGetSymbolAddress((void**)&k2,   g_k2);
    cudaGetSymbolAddress((void**)&v2,   g_v2);
    cudaGetSymbolAddress((void**)&cat,  g_cat);
    cudaGetSymbolAddress((void**)&cat2, g_cat2);
    cudaGetSymbolAddress((void**)&O2p,  g_O2p);
    cudaGetSymbolAddress((void**)&l2,   g_l2);

    mod_kernel<<<3 * HID, 256>>>(vec, mw, mb, m);

    // ================= Block 1 =================
    ln_mod_kernel<<<LX, 256>>>(x, xm, m);

    // qkv part of h
    tc_gemm<256, 4, 0><<<dim3(QKVW / 256, LX / 128, 1), 256, SM256>>>(
        xm, w1, h, HID, HID, HID, QKVW, 0, 0, 0, b1, nullptr, 0, nullptr, LX);
    // mlp part -> gelu -> cat[:,HID:]
    tc_gemm<256, 4, 2><<<dim3(MLP / 256, LX / 128, 1), 256, SM256>>>(
        xm, w1 + (size_t)QKVW * HID, cat + HID, HID, HID, HID, CATW,
        0, 0, 0, b1 + QKVW, nullptr, 0, nullptr, LX);

    dim3 gqk(LX, NH);
    rmsrope_kernel<<<gqk, HD>>>(h + 0,       QKVW, pe, qs,      1, q, LX, 0, SOFT_SCALE);
    rmsrope_kernel<<<gqk, HD>>>(h + HID,     QKVW, pe, ks,      1, k, LX, 0, 1.f);
    rmsrope_kernel<<<gqk, HD>>>(h + 2 * HID, QKVW, pe, nullptr, 0, v, LX, 1, 1.f);

    // fused attention -> cat[:,0:HID]
    flash_kernel<0><<<dim3(LX / 128, NH), 256, FL_SMEM>>>(
        q, k, v, cat, nullptr,
        (size_t)LX * HD, (size_t)LX * HD, (size_t)HD * LX, LX,
        LX / 64, LX, CATW);

    // out_x = x + gate * (cat @ w2.T + b2)
    tc_gemm<256, 4, 1><<<dim3(HID / 256, LX / 128, 1), 256, SM256>>>(
        cat, w2, out, CATW, CATW, CATW, HID, 0, 0, 0, b2, x, HID, m + 2 * HID, LX);

    // ================= Block 2 =================
    ln_mod_kernel<<<NC, 256>>>(cps, xm, m);
    ln_mod_kernel<<<4096, 256>>>(x + (size_t)256 * HID, xm + (size_t)NC * HID, m);

    // k,v cols for all rows
    tc_gemm<256, 4, 0><<<dim3(3072 / 256, L2P / 128, 1), 256, SM256>>>(
        xm, w1 + (size_t)HID * HID, h2kv, HID, HID, HID, 3072,
        0, 0, 0, b1 + HID, nullptr, 0, nullptr, L2P);
    // q cols for first 128 rows
    tc_gemm<256, 4, 0><<<dim3(HID / 256, 1, 1), 256, SM256>>>(
        xm, w1, h2f, HID, HID, HID, HID, 0, 0, 0, b1, nullptr, 0, nullptr, 128);
    // mlp cols (gelu) for first 128 rows -> cat2[:,HID:]
    tc_gemm<256, 4, 2><<<dim3(MLP / 256, 1, 1), 256, SM256>>>(
        xm, w1 + (size_t)QKVW * HID, cat2 + HID, HID, HID, HID, CATW,
        0, 0, 0, b1 + QKVW, nullptr, 0, nullptr, 128);

    dim3 gk2(L2V, NH);
    rmsrope_kernel<<<gk2, HD>>>(h2kv + 0,   3072, cpe, ks,      1, k2, L2P, 0, 1.f);
    rmsrope_kernel<<<gk2, HD>>>(h2kv + HID, 3072, cpe, nullptr, 0, v2, L2P, 1, 1.f);
    rmsrope_kernel<<<dim3(NC, NH), HD>>>(h2f, HID, cpe, qs, 1, q2, 128, 0, SOFT_SCALE);

    // split-K fused attention
    flash_kernel<1><<<dim3(NSPLIT, NH), 256, FL_SMEM>>>(
        q2, k2, v2, O2p, l2,
        (size_t)128 * HD, (size_t)L2P * HD, (size_t)HD * L2P, L2P,
        L2P / 64 / NSPLIT, L2V, 0);
    combine2_kernel<<<dim3(NC, NH), HD>>>(O2p, l2, cat2);

    // concepts_out = concepts + gate * (cat2 @ w2.T + b2)
    tc_gemm<256, 4, 1><<<dim3(HID / 256, 1, 1), 256, SM256>>>(
        cat2, w2, out + (size_t)LX * HID, CATW, CATW, CATW, HID,
        0, 0, 0, b2, cps, HID, m + 2 * HID, NC);
}

// round 12
// speedup vs baseline: 8.5875x; 1.0210x over previous
#include <cuda_runtime.h>
#include <cuda_bf16.h>
#include <cstdint>
#include <cstddef>

#define HID     1536
#define NH      12
#define HD      128
#define MLP     6144
#define LX      4352
#define NC      20
#define L2V     4116
#define L2P     4352
#define QKVW    4608
#define CATW    7680
#define NSPLIT  4
#define SOFT_SCALE 0.08838834764831845f

typedef unsigned int u32;
typedef unsigned long long u64;

#if defined(__CUDA_ARCH_FEAT_SM103_ALL) || defined(__CUDA_ARCH_FEAT_SM100_ALL) || defined(__CUDA_ARCH_FEAT_SM101_ALL)
#define HAS_TCGEN05 1
#else
#define HAS_TCGEN05 0
#endif

// ---------------- scratch ----------------
__device__ __align__(256) float g_m[3 * HID];
__device__ __align__(256) float g_xm[(size_t)LX * HID];
__device__ __align__(256) float g_h[(size_t)LX * QKVW];
__device__ __align__(256) float g_h2kv[(size_t)L2P * 3072];
__device__ __align__(256) float g_h2f[(size_t)128 * HID];
__device__ __align__(256) float g_q[(size_t)NH * LX * HD];
__device__ __align__(256) float g_k[(size_t)NH * LX * HD];
__device__ __align__(256) float g_v[(size_t)NH * HD * LX];      // vT [h][d][l]
__device__ __align__(256) float g_q2[(size_t)NH * 128 * HD];
__device__ __align__(256) float g_k2[(size_t)NH * L2P * HD];
__device__ __align__(256) float g_v2[(size_t)NH * HD * L2P];
__device__ __align__(256) float g_cat[(size_t)LX * CATW];
__device__ __align__(256) float g_cat2[(size_t)128 * CATW];
__device__ __align__(256) float g_O2p[(size_t)NSPLIT * NH * 128 * HD];
__device__ __align__(256) float g_l2[(size_t)NSPLIT * NH * 128];

// ---------------- PTX helpers ----------------
__device__ __forceinline__ u32 s2u(const void* p) { return (u32)__cvta_generic_to_shared(p); }
__device__ __forceinline__ u32 swz(u32 o) { return o ^ ((o >> 3) & 0x70); }
__device__ __forceinline__ void cp16(u32 dst, const void* src) {
    asm volatile("cp.async.cg.shared.global [%0], [%1], 16;" :: "r"(dst), "l"(src));
}
__device__ __forceinline__ void cp_commit() { asm volatile("cp.async.commit_group;" ::: "memory"); }
template <int N> __device__ __forceinline__ void cp_wait() {
    asm volatile("cp.async.wait_group %0;" :: "n"(N) : "memory");
}
__device__ __forceinline__ bool elect1() {
    u32 p;
    asm volatile("{\n\t.reg .pred p;\n\telect.sync _|p, 0xFFFFFFFF;\n\tselp.b32 %0,1,0,p;\n\t}" : "=r"(p));
    return p != 0;
}
__device__ __forceinline__ u64 sdesc(u32 addr) {
    return 0x4000404000010000ull | (u64)((addr >> 4) & 0x3FFF);
}
__device__ __forceinline__ void mbar_init(u32 a) {
    u32 one = 1;
    asm volatile("mbarrier.init.shared.b64 [%0], %1;" :: "r"(a), "r"(one) : "memory");
}
__device__ __forceinline__ void mbar_wait(u32 a, u32 parity) {
    asm volatile(
        "{\n\t.reg .pred P;\n"
        "LW_%=:\n\t"
        "mbarrier.try_wait.parity.acquire.cta.shared::cta.b64 P, [%0], %1, 0x989680;\n\t"
        "@P bra LD_%=;\n\t"
        "bra LW_%=;\n"
        "LD_%=:\n\t}" :: "r"(a), "r"(parity) : "memory");
}
__device__ __forceinline__ void fence_async_shared() {
    asm volatile("fence.proxy.async.shared::cta;" ::: "memory");
}
__device__ __forceinline__ void tc_commit(u32 mbar) {
#if HAS_TCGEN05
    asm volatile("tcgen05.commit.cta_group::1.mbarrier::arrive::one.shared::cluster.b64 [%0];"
                 :: "r"(mbar) : "memory");
#else
    (void)mbar;
#endif
}
__device__ __forceinline__ void mma_tf32(u32 d, u64 ad, u64 bd, u32 idesc, u32 en) {
#if HAS_TCGEN05
    asm volatile(
        "{\n\t.reg .pred p;\n\tsetp.ne.u32 p, %4, 0;\n\t"
        "tcgen05.mma.cta_group::1.kind::tf32 [%0], %1, %2, %3, {%5,%5,%5,%5}, p;\n\t}"
        :: "r"(d), "l"(ad), "l"(bd), "r"(idesc), "r"(en), "r"(0u) : "memory");
#else
    (void)d; (void)ad; (void)bd; (void)idesc; (void)en;
#endif
}
__device__ __forceinline__ void tc_fence_after() {
#if HAS_TCGEN05
    asm volatile("tcgen05.fence::after_thread_sync;" ::: "memory");
#endif
}
__device__ __forceinline__ void tc_fence_before() {
#if HAS_TCGEN05
    asm volatile("tcgen05.fence::before_thread_sync;" ::: "memory");
#endif
}
__device__ __forceinline__ void tmem_alloc(u32 dst_smem, u32 ncols) {
#if HAS_TCGEN05
    asm volatile("tcgen05.alloc.cta_group::1.sync.aligned.shared::cta.b32 [%0], %1;"
                 :: "r"(dst_smem), "r"(ncols) : "memory");
#else
    (void)dst_smem; (void)ncols;
#endif
}
__device__ __forceinline__ void tmem_relinquish() {
#if HAS_TCGEN05
    asm volatile("tcgen05.relinquish_alloc_permit.cta_group::1.sync.aligned;");
#endif
}
__device__ __forceinline__ void tmem_dealloc(u32 tmem, u32 ncols) {
#if HAS_TCGEN05
    asm volatile("tcgen05.dealloc.cta_group::1.sync.aligned.b32 %0, %1;" :: "r"(tmem), "r"(ncols));
#else
    (void)tmem; (void)ncols;
#endif
}
__device__ __forceinline__ void tmem_wait_ld() {
#if HAS_TCGEN05
    asm volatile("tcgen05.wait::ld.sync.aligned;" ::: "memory");
#endif
}
__device__ __forceinline__ void ldtm32(u32* r, u32 a) {
#if HAS_TCGEN05
    asm volatile(
        "tcgen05.ld.sync.aligned.32x32b.x32.b32 "
        "{%0, %1, %2, %3, %4, %5, %6, %7, "
        " %8, %9, %10, %11, %12, %13, %14, %15, "
        " %16, %17, %18, %19, %20, %21, %22, %23, "
        " %24, %25, %26, %27, %28, %29, %30, %31}, [%32];"
        : "=r"(r[0]),  "=r"(r[1]),  "=r"(r[2]),  "=r"(r[3]),
          "=r"(r[4]),  "=r"(r[5]),  "=r"(r[6]),  "=r"(r[7]),
          "=r"(r[8]),  "=r"(r[9]),  "=r"(r[10]), "=r"(r[11]),
          "=r"(r[12]), "=r"(r[13]), "=r"(r[14]), "=r"(r[15]),
          "=r"(r[16]), "=r"(r[17]), "=r"(r[18]), "=r"(r[19]),
          "=r"(r[20]), "=r"(r[21]), "=r"(r[22]), "=r"(r[23]),
          "=r"(r[24]), "=r"(r[25]), "=r"(r[26]), "=r"(r[27]),
          "=r"(r[28]), "=r"(r[29]), "=r"(r[30]), "=r"(r[31])
        : "r"(a));
#else
#pragma unroll
    for (int i = 0; i < 32; ++i) r[i] = 0u;
    (void)a;
#endif
}
__device__ __forceinline__ float gelu_f(float x) {
    float u = 0.7978845608028654f * (x + 0.044715f * x * x * x);
    return 0.5f * x * (1.f + tanhf(u));
}

// ---------------------------------------------------------------------------
// tc_gemm2: tf32 SS GEMM (NT), CTA tile 256 x 256 (two M=128 accumulators
// sharing one B tile => half the B traffic). Grid: (N/256, M/256).
// EPI 0: +bias. 1: res + gate*(acc+bias). 2: gelu(acc+bias).
// ---------------------------------------------------------------------------
#define G2_STAGES 3
#define G2_STRIDE 65536
#define SMEM_G2 (1024 + G2_STAGES * G2_STRIDE)

template <int EPI>
__global__ __launch_bounds__(256, 1)
void tc_gemm2(const float* __restrict__ A, const float* __restrict__ B, float* __restrict__ C,
              int K, int lda, int ldb, int ldc,
              const float* __restrict__ bias,
              const float* __restrict__ res, int ldres,
              const float* __restrict__ gate, int Mstore)
{
    constexpr u32 IDESC = (1u << 4) | (2u << 7) | (2u << 10) | (32u << 17) | (8u << 24);

    extern __shared__ char smem[];
    const u32 sb = s2u(smem);
    const u32 mb0 = sb + 8;
    const u32 tile0 = sb + 1024;

    const int bm = blockIdx.y * 256;
    const int bn = blockIdx.x * 256;
    const int tid = threadIdx.x;

    if (tid == 0)
        for (int s = 0; s < G2_STAGES; ++s) mbar_init(mb0 + 8 * s);
    if (tid < 32) { tmem_alloc(sb, 512); tmem_relinquish(); }
    __syncthreads();
    u32 tmem;
    asm volatile("ld.shared.b32 %0, [%1];" : "=r"(tmem) : "r"(sb));

    const int nk = K >> 5;

#define G2_LOAD(pp, st)                                                        \
    do {                                                                       \
        _Pragma("unroll")                                                      \
        for (int i = 0; i < 8; ++i) {      /* A: 256 rows x 128B */            \
            int o = tid + (i << 8);                                            \
            int r_ = o >> 3, c_ = o & 7;                                       \
            cp16((st) + ((u32)(r_ >> 7) << 14) +                               \
                     swz((u32)(((r_ & 127) << 7) + (c_ << 4))),                \
                 A + (size_t)(bm + r_) * lda + ((pp) << 5) + (c_ << 2));       \
        }                                                                      \
        _Pragma("unroll")                                                      \
        for (int i = 0; i < 8; ++i) {      /* B: 256 rows x 128B */            \
            int o = tid + (i << 8);                                            \
            int r_ = o >> 3, c_ = o & 7;                                       \
            cp16((st) + 32768u + swz((u32)((r_ << 7) + (c_ << 4))),            \
                 B + (size_t)(bn + r_) * ldb + ((pp) << 5) + (c_ << 2));       \
        }                                                                      \
    } while (0)

    for (int p = 0; p < G2_STAGES - 1; ++p) {
        if (p < nk) G2_LOAD(p, tile0 + (u32)p * G2_STRIDE);
        cp_commit();
    }

    for (int it = 0; it < nk; ++it) {
        const int b = it % G2_STAGES;
        cp_wait<G2_STAGES - 2>();
        fence_async_shared();
        __syncthreads();

        if (tid < 32 && elect1()) {
            u64 da0 = sdesc(tile0 + (u32)b * G2_STRIDE);
            u64 da1 = sdesc(tile0 + (u32)b * G2_STRIDE + 16384u);
            u64 db  = sdesc(tile0 + (u32)b * G2_STRIDE + 32768u);
#pragma unroll
            for (int j = 0; j < 4; ++j) {
                u32 en = (u32)((it > 0) || (j > 0));
                mma_tf32(tmem,       da0 + j * 2, db + j * 2, IDESC, en);
                mma_tf32(tmem + 256, da1 + j * 2, db + j * 2, IDESC, en);
            }
            tc_commit(mb0 + 8 * b);
        }

        const int p = it + G2_STAGES - 1;
        if (p < nk) {
            if (it >= 1)
                mbar_wait(mb0 + 8 * (p % G2_STAGES), (u32)(((it - 1) / G2_STAGES) & 1));
            G2_LOAD(p, tile0 + (u32)(p % G2_STAGES) * G2_STRIDE);
        }
        cp_commit();
    }
#undef G2_LOAD

    mbar_wait(mb0 + 8 * ((nk - 1) % G2_STAGES), (u32)(((nk - 1) / G2_STAGES) & 1));
    tc_fence_after();

    {
        const int w = tid >> 5, lane = tid & 31;
        const int accsel = w >> 2;
        const int row = bm + accsel * 128 + (w & 3) * 32 + lane;
        const bool doSt = row < Mstore;
        float* crow = C + (size_t)row * ldc;
        const float* rrow = (EPI == 1 && doSt) ? (res + (size_t)row * ldres) : nullptr;
        const u32 tbase = tmem + (u32)accsel * 256;
#pragma unroll
        for (int g = 0; g < 8; ++g) {
            u32 regs[32];
            ldtm32(regs, tbase + g * 32);
            tmem_wait_ld();
            if (doSt) {
#pragma unroll
                for (int q4 = 0; q4 < 8; ++q4) {
                    int col = bn + g * 32 + q4 * 4;
                    float4 vv;
                    vv.x = __uint_as_float(regs[q4 * 4 + 0]);
                    vv.y = __uint_as_float(regs[q4 * 4 + 1]);
                    vv.z = __uint_as_float(regs[q4 * 4 + 2]);
                    vv.w = __uint_as_float(regs[q4 * 4 + 3]);
                    if (bias) {
                        float4 bb = *(const float4*)(bias + col);
                        vv.x += bb.x; vv.y += bb.y; vv.z += bb.z; vv.w += bb.w;
                    }
                    if (EPI == 1) {
                        float4 rr = *(const float4*)(rrow + col);
                        float4 gg = *(const float4*)(gate + col);
                        vv.x = rr.x + gg.x * vv.x; vv.y = rr.y + gg.y * vv.y;
                        vv.z = rr.z + gg.z * vv.z; vv.w = rr.w + gg.w * vv.w;
                    } else if (EPI == 2) {
                        vv.x = gelu_f(vv.x); vv.y = gelu_f(vv.y);
                        vv.z = gelu_f(vv.z); vv.w = gelu_f(vv.w);
                    }
                    *(float4*)(crow + col) = vv;
                }
            }
        }
    }
    __syncthreads();
    if (tid < 32) tmem_dealloc(tmem, 512);
}

// ---------------------------------------------------------------------------
// tc_gemm: original 128 x BN tile (kept for M=128 block-2 GEMMs)
// ---------------------------------------------------------------------------
template <int BN>
__device__ __forceinline__ void load_chunk(u32 st, const float* A, const float* B,
                                           int bm, int bn, int kt, int lda, int ldb, int tid)
{
#pragma unroll
    for (int i = 0; i < 4; ++i) {
        int o = tid + (i << 8);
        int r = o >> 3, c = o & 7;
        cp16(st + swz((u32)((r << 7) + (c << 4))),
             A + (size_t)(bm + r) * lda + kt + (c << 2));
    }
    const u32 stB = st + 128 * 128;
#pragma unroll
    for (int i = 0; i < BN / 32; ++i) {
        int o = tid + (i << 8);
        int r = o >> 3, c = o & 7;
        cp16(stB + swz((u32)((r << 7) + (c << 4))),
             B + (size_t)(bn + r) * ldb + kt + (c << 2));
    }
}

template <int BN, int STAGES, int EPI>
__global__ __launch_bounds__(256, 1)
void tc_gemm(const float* __restrict__ A, const float* __restrict__ B, float* __restrict__ C,
             int K, int lda, int ldb, int ldc,
             size_t sA, size_t sB, size_t sC,
             const float* __restrict__ bias,
             const float* __restrict__ res, int ldres,
             const float* __restrict__ gate, int Mstore)
{
    constexpr int ASZ = 128 * 128;
    constexpr int STRIDE = ASZ + BN * 128;
    constexpr u32 IDESC = (1u << 4) | (2u << 7) | (2u << 10) |
                          ((u32)(BN / 8) << 17) | (8u << 24);

    extern __shared__ char smem[];
    const u32 sb = s2u(smem);
    const u32 mb0 = sb + 8;
    const u32 tile0 = sb + 1024;

    A += (size_t)blockIdx.z * sA;
    B += (size_t)blockIdx.z * sB;
    C += (size_t)blockIdx.z * sC;
    const int bm = blockIdx.y * 128;
    const int bn = blockIdx.x * BN;
    const int tid = threadIdx.x;

    if (tid == 0)
        for (int s = 0; s < STAGES; ++s) mbar_init(mb0 + 8 * s);
    if (tid < 32) { tmem_alloc(sb, BN); tmem_relinquish(); }
    __syncthreads();
    u32 tmem;
    asm volatile("ld.shared.b32 %0, [%1];" : "=r"(tmem) : "r"(sb));

    const int nk = K >> 5;
    for (int p = 0; p < STAGES - 1; ++p) {
        if (p < nk)
            load_chunk<BN>(tile0 + (p % STAGES) * STRIDE, A, B, bm, bn, p << 5, lda, ldb, tid);
        cp_commit();
    }

    for (int it = 0; it < nk; ++it) {
        const int b = it % STAGES;
        cp_wait<STAGES - 2>();
        fence_async_shared();
        __syncthreads();

        if (tid < 32) {
            u64 da = sdesc(tile0 + b * STRIDE);
            u64 db = sdesc(tile0 + b * STRIDE + ASZ);
            if (elect1()) {
#pragma unroll
                for (int j = 0; j < 4; ++j)
                    mma_tf32(tmem, da + j * 2, db + j * 2, IDESC, (u32)((it > 0) || (j > 0)));
                tc_commit(mb0 + 8 * b);
            }
        }
        const int p = it + STAGES - 1;
        if (p < nk) {
            if (it >= 1)
                mbar_wait(mb0 + 8 * (p % STAGES), (u32)(((it - 1) / STAGES) & 1));
            load_chunk<BN>(tile0 + (p % STAGES) * STRIDE, A, B, bm, bn, p << 5, lda, ldb, tid);
        }
        cp_commit();
    }

    mbar_wait(mb0 + 8 * ((nk - 1) % STAGES), (u32)(((nk - 1) / STAGES) & 1));
    tc_fence_after();

    if (tid < 128) {
        const int w = tid >> 5, lane = tid & 31;
        const int row = bm + w * 32 + lane;
        const bool doSt = row < Mstore;
        float* crow = C + (size_t)row * ldc;
        const float* rrow = (EPI == 1 && doSt) ? (res + (size_t)row * ldres) : nullptr;
#pragma unroll
        for (int g = 0; g < BN / 32; ++g) {
            u32 regs[32];
            ldtm32(regs, tmem + g * 32);
            tmem_wait_ld();
            if (doSt) {
#pragma unroll
                for (int q4 = 0; q4 < 8; ++q4) {
                    int col = bn + g * 32 + q4 * 4;
                    float4 vv;
                    vv.x = __uint_as_float(regs[q4 * 4 + 0]);
                    vv.y = __uint_as_float(regs[q4 * 4 + 1]);
                    vv.z = __uint_as_float(regs[q4 * 4 + 2]);
                    vv.w = __uint_as_float(regs[q4 * 4 + 3]);
                    if (bias) {
                        float4 bb = *(const float4*)(bias + col);
                        vv.x += bb.x; vv.y += bb.y; vv.z += bb.z; vv.w += bb.w;
                    }
                    if (EPI == 1) {
                        float4 rr = *(const float4*)(rrow + col);
                        float4 gg = *(const float4*)(gate + col);
                        vv.x = rr.x + gg.x * vv.x; vv.y = rr.y + gg.y * vv.y;
                        vv.z = rr.z + gg.z * vv.z; vv.w = rr.w + gg.w * vv.w;
                    } else if (EPI == 2) {
                        vv.x = gelu_f(vv.x); vv.y = gelu_f(vv.y);
                        vv.z = gelu_f(vv.z); vv.w = gelu_f(vv.w);
                    }
                    *(float4*)(crow + col) = vv;
                }
            }
        }
    }
    __syncthreads();
    if (tid < 32) tmem_dealloc(tmem, BN);
}

// ---------------- flash attention ----------------
__device__ __forceinline__ void ld_ktile(u32 dstb, const float* Kb, int jt, int tid) {
#pragma unroll
    for (int i = 0; i < 8; ++i) {
        int o = tid + (i << 8);
        int row = o >> 5, inner = o & 31, c = inner >> 3, s = inner & 7;
        cp16(dstb + c * 8192 + swz((u32)((row << 7) + (s << 4))),
             Kb + (size_t)(jt * 64 + row) * HD + (c << 5) + (s << 2));
    }
}
__device__ __forceinline__ void ld_vtile(u32 dstb, const float* Vb, int jt, int vLD, int tid) {
#pragma unroll
    for (int i = 0; i < 8; ++i) {
        int o = tid + (i << 8);
        int row = o >> 4, inner = o & 15, c = inner >> 3, s = inner & 7;
        cp16(dstb + c * 16384 + swz((u32)((row << 7) + (s << 4))),
             Vb + (size_t)row * vLD + jt * 64 + (c << 5) + (s << 2));
    }
}
#define IDESC_QK ((1u << 4) | (2u << 7) | (2u << 10) | (8u << 17) | (8u << 24))
#define IDESC_PV ((1u << 4) | (2u << 7) | (2u << 10) | (16u << 17) | (8u << 24))

__device__ __forceinline__ void issue_qk(u32 dcol, u32 sQ, u32 sKb) {
#pragma unroll
    for (int c = 0; c < 4; ++c) {
        u64 da = sdesc(sQ + c * 16384);
        u64 db = sdesc(sKb + c * 8192);
#pragma unroll
        for (int j = 0; j < 4; ++j)
            mma_tf32(dcol, da + j * 2, db + j * 2, IDESC_QK, (u32)((c | j) != 0));
    }
}
__device__ __forceinline__ void issue_pv(u32 dcol, u32 sPb, u32 sVb, bool first) {
#pragma unroll
    for (int c = 0; c < 2; ++c) {
        u64 da = sdesc(sPb + c * 16384);
        u64 db = sdesc(sVb + c * 16384);
#pragma unroll
        for (int j = 0; j < 4; ++j)
            mma_tf32(dcol, da + j * 2, db + j * 2, IDESC_PV,
                     (u32)(!(first && c == 0 && j == 0)));
    }
}

#define FL_SMEM (2048 + 65536 + 65536 + 65536 + 32768)

template <int SPLITOUT>
__global__ __launch_bounds__(256, 1)
void flash_kernel(const float* __restrict__ Qg, const float* __restrict__ Kg,
                  const float* __restrict__ Vg,
                  float* __restrict__ dst, float* __restrict__ lout,
                  size_t qHS, size_t kHS, size_t vHS, int vLD,
                  int nt, int nvalid, int ldd)
{
    extern __shared__ char smem[];
    float* rowsum = (float*)(smem + 16);
    const u32 sb = s2u(smem);
    const u32 mbar = sb + 8;
    const u32 sQ = sb + 2048;
    const u32 sK = sQ + 65536;
    const u32 sV = sK + 65536;
    const u32 sP = sV + 65536;

    const int h = blockIdx.y;
    const int tid = threadIdx.x;
    const int wid = tid >> 5, lane = tid & 31;
    const int hf = wid >> 2;
    const int r = ((wid & 3) << 5) + lane;
    const int t0 = SPLITOUT ? blockIdx.x * nt : 0;
    const int bm = SPLITOUT ? 0 : blockIdx.x * 128;

    const float* Qb = Qg + (size_t)h * qHS + (size_t)bm * HD;
    const float* Kb = Kg + (size_t)h * kHS;
    const float* Vb = Vg + (size_t)h * vHS;

#pragma unroll
    for (int i = 0; i < 16; ++i) {
        int o = tid + (i << 8);
        int row = o >> 5, inner = o & 31, c = inner >> 3, s = inner & 7;
        cp16(sQ + c * 16384 + swz((u32)((row << 7) + (s << 4))),
             Qb + (size_t)row * HD + (c << 5) + (s << 2));
    }
    ld_ktile(sK, Kb, t0, tid);
    ld_vtile(sV, Vb, t0, vLD, tid);
    cp_commit();
    if (nt > 1) ld_ktile(sK + 32768, Kb, t0 + 1, tid);
    cp_commit();

    if (tid == 0) mbar_init(mbar);
    if (tid < 32) { tmem_alloc(sb, 256); tmem_relinquish(); }
    __syncthreads();
    u32 tmem;
    asm volatile("ld.shared.b32 %0, [%1];" : "=r"(tmem) : "r"(sb));
    const u32 tO = tmem;

    cp_wait<1>();
    fence_async_shared();
    __syncthreads();
    if (tid < 32 && elect1()) {
        issue_qk(tmem + 128, sQ, sK);
        tc_commit(mbar);
    }

    float lacc = 0.f;
    u32 par = 0;

    for (int t = 0; t < nt; ++t) {
        const u32 scol = 128 + ((u32)(t & 1) << 6);

        mbar_wait(mbar, par); par ^= 1;
        tc_fence_after();
        cp_wait<0>();
        fence_async_shared();
        __syncthreads();

        if (tid < 32 && elect1()) {
            if (t + 1 < nt)
                issue_qk(tmem + 128 + ((u32)((t + 1) & 1) << 6),
                         sQ, sK + ((u32)((t + 1) & 1) * 32768u));
        }
        if (t + 2 < nt) ld_ktile(sK + ((u32)(t & 1) * 32768u), Kb, t0 + t + 2, tid);
        if (t + 1 < nt) ld_vtile(sV + ((u32)((t + 1) & 1) * 32768u), Vb, t0 + t + 1, vLD, tid);
        cp_commit();

        u32 sr[32];
        ldtm32(sr, tmem + scol + ((u32)hf << 5));
        tmem_wait_ld();
        float p[32];
        float ls = 0.f;
        const int jb = (t0 + t) * 64 + (hf << 5);
#pragma unroll
        for (int i = 0; i < 32; ++i) {
            float sv = __uint_as_float(sr[i]);
            float e = (jb + i < nvalid) ? __expf(sv) : 0.f;
            p[i] = e; ls += e;
        }
        lacc += ls;

        const u32 pbase = sP + (hf ? 16384u : 0u);
#pragma unroll
        for (int g = 0; g < 8; ++g) {
            u32 addr = pbase + swz(((u32)r << 7) + ((u32)g << 4));
            asm volatile("st.shared.v4.b32 [%0], {%1,%2,%3,%4};" :: "r"(addr),
                "r"(__float_as_uint(p[4 * g + 0])), "r"(__float_as_uint(p[4 * g + 1])),
                "r"(__float_as_uint(p[4 * g + 2])), "r"(__float_as_uint(p[4 * g + 3]))
                : "memory");
        }
        tc_fence_before();
        fence_async_shared();
        __syncthreads();

        if (tid < 32 && elect1()) {
            tc_fence_after();
            issue_pv(tO, sP, sV + ((u32)(t & 1) * 32768u), t == 0);
            tc_commit(mbar);
        }
    }

    mbar_wait(mbar, par);
    tc_fence_after();

    rowsum[r * 2 + hf] = lacc;
    __syncthreads();
    const float ltot = rowsum[r * 2] + rowsum[r * 2 + 1];

    if (SPLITOUT) {
        float* od = dst + (((size_t)blockIdx.x * NH + h) * 128 + r) * HD + (hf << 6);
#pragma unroll
        for (int g2 = 0; g2 < 2; ++g2) {
            u32 orgs[32];
            ldtm32(orgs, tO + ((u32)hf << 6) + ((u32)g2 << 5));
            tmem_wait_ld();
#pragma unroll
            for (int i = 0; i < 8; ++i) {
                float4 vv;
                vv.x = __uint_as_float(orgs[i * 4 + 0]);
                vv.y = __uint_as_float(orgs[i * 4 + 1]);
                vv.z = __uint_as_float(orgs[i * 4 + 2]);
                vv.w = __uint_as_float(orgs[i * 4 + 3]);
                *(float4*)(od + (g2 << 5) + i * 4) = vv;
            }
        }
        if (hf == 0)
            lout[((size_t)blockIdx.x * NH + h) * 128 + r] = ltot;
    } else {
        const float inv = 1.f / ltot;
        float* od = dst + (size_t)(bm + r) * ldd + h * HD + (hf << 6);
#pragma unroll
        for (int g2 = 0; g2 < 2; ++g2) {
            u32 orgs[32];
            ldtm32(orgs, tO + ((u32)hf << 6) + ((u32)g2 << 5));
            tmem_wait_ld();
#pragma unroll
            for (int i = 0; i < 8; ++i) {
                float4 vv;
                vv.x = __uint_as_float(orgs[i * 4 + 0]) * inv;
                vv.y = __uint_as_float(orgs[i * 4 + 1]) * inv;
                vv.z = __uint_as_float(orgs[i * 4 + 2]) * inv;
                vv.w = __uint_as_float(orgs[i * 4 + 3]) * inv;
                *(float4*)(od + (g2 << 5) + i * 4) = vv;
            }
        }
    }
    tc_fence_before();
    __syncthreads();
    if (tid < 32) tmem_dealloc(tmem, 256);
}

__global__ void combine2_kernel(const float* __restrict__ Op, const float* __restrict__ lp,
                                float* __restrict__ cat2)
{
    int r = blockIdx.x, h = blockIdx.y, d = threadIdx.x;
    float o = 0.f, l = 0.f;
#pragma unroll
    for (int s = 0; s < NSPLIT; ++s) {
        o += Op[(((size_t)s * NH + h) * 128 + r) * HD + d];
        l += lp[((size_t)s * NH + h) * 128 + r];
    }
    cat2[(size_t)r * CATW + h * HD + d] = o / l;
}

// ---------------- small elementwise kernels ----------------
__global__ void mod_kernel(const float* __restrict__ vec, const float* __restrict__ mw,
                           const float* __restrict__ mb, float* __restrict__ m)
{
    int o = blockIdx.x, t = threadIdx.x;
    float s = 0.f;
    for (int k = t; k < HID; k += 256) {
        float v = vec[k];
        s += (v / (1.f + expf(-v))) * mw[(size_t)o * HID + k];
    }
    __shared__ float red[256];
    red[t] = s; __syncthreads();
    for (int st = 128; st > 0; st >>= 1) { if (t < st) red[t] += red[t + st]; __syncthreads(); }
    if (t == 0) m[o] = red[0] + mb[o];
}

__global__ void ln_mod_kernel(const float* __restrict__ in, float* __restrict__ out,
                              const float* __restrict__ m)
{
    int row = blockIdx.x, t = threadIdx.x;
    const float* x = in + (size_t)row * HID;
    __shared__ float buf[HID];
    __shared__ float red[256];

    float s = 0.f;
    for (int c = t; c < HID; c += 256) { float v = x[c]; buf[c] = v; s += v; }
    red[t] = s; __syncthreads();
    for (int st = 128; st > 0; st >>= 1) { if (t < st) red[t] += red[t + st]; __syncthreads(); }
    float mu = red[0] * (1.f / HID);
    __syncthreads();

    float ss = 0.f;
    for (int c = t; c < HID; c += 256) { float d = buf[c] - mu; ss += d * d; }
    red[t] = ss; __syncthreads();
    for (int st = 128; st > 0; st >>= 1) { if (t < st) red[t] += red[t + st]; __syncthreads(); }
    float inv = rsqrtf(red[0] * (1.f / HID) + 1e-6f);

    float* o = out + (size_t)row * HID;
    for (int c = t; c < HID; c += 256)
        o[c] = (1.f + m[HID + c]) * ((buf[c] - mu) * inv) + m[c];
}

__global__ void rmsrope_kernel(const float* __restrict__ src, int ldh,
                               const float* __restrict__ pe,
                               const float* __restrict__ scale, int dorope,
                               float* __restrict__ dst, int dstL, int transp,
                               float premul)
{
    int l = blockIdx.x, hd = blockIdx.y, d = threadIdx.x;
    float v = src[(size_t)l * ldh + hd * HD + d];
    __shared__ float sv[HD];
    __shared__ float wred[4];

    if (scale) {
        float ss = v * v;
#pragma unroll
        for (int o = 16; o > 0; o >>= 1) ss += __shfl_xor_sync(0xffffffffu, ss, o);
        if ((d & 31) == 0) wred[d >> 5] = ss;
        __syncthreads();
        float tot = wred[0] + wred[1] + wred[2] + wred[3];
        v = v * rsqrtf(tot * (1.f / HD) + 1e-6f) * scale[d] * premul;
        __syncthreads();
    }
    float outv;
    if (dorope) {
        sv[d] = v; __syncthreads();
        int i = d >> 1, j = d & 1;
        const float* pp = pe + (size_t)l * 256 + i * 4 + j * 2;
        outv = pp[0] * sv[2 * i] + pp[1] * sv[2 * i + 1];
    } else {
        outv = v;
    }
    if (transp)
        dst[((size_t)hd * HD + d) * dstL + l] = outv;
    else
        dst[((size_t)hd * dstL + l) * HD + d] = outv;
}

// ---------------- launch ----------------
#define SMEM_FOR(BN, S) (1024 + (S) * ((128 * 128) + (BN) * 128))

extern "C" void kernel_launch(void* const* d_in, const int* in_sizes, int n_in,
                              void* d_out, int out_size)
{
    (void)in_sizes; (void)n_in; (void)out_size;
    const float* x   = (const float*)d_in[0];
    const float* cps = (const float*)d_in[1];
    const float* vec = (const float*)d_in[2];
    const float* pe  = (const float*)d_in[3];
    const float* cpe = (const float*)d_in[4];
    const float* w1  = (const float*)d_in[5];
    const float* b1  = (const float*)d_in[6];
    const float* w2  = (const float*)d_in[7];
    const float* b2  = (const float*)d_in[8];
    const float* qs  = (const float*)d_in[9];
    const float* ks  = (const float*)d_in[10];
    const float* mw  = (const float*)d_in[11];
    const float* mb  = (const float*)d_in[12];
    float* out = (float*)d_out;

    const int SM256 = SMEM_FOR(256, 4);
    cudaFuncSetAttribute(tc_gemm<256, 4, 0>, cudaFuncAttributeMaxDynamicSharedMemorySize, SM256);
    cudaFuncSetAttribute(tc_gemm<256, 4, 1>, cudaFuncAttributeMaxDynamicSharedMemorySize, SM256);
    cudaFuncSetAttribute(tc_gemm<256, 4, 2>, cudaFuncAttributeMaxDynamicSharedMemorySize, SM256);
    cudaFuncSetAttribute(tc_gemm2<0>, cudaFuncAttributeMaxDynamicSharedMemorySize, SMEM_G2);
    cudaFuncSetAttribute(tc_gemm2<1>, cudaFuncAttributeMaxDynamicSharedMemorySize, SMEM_G2);
    cudaFuncSetAttribute(tc_gemm2<2>, cudaFuncAttributeMaxDynamicSharedMemorySize, SMEM_G2);
    cudaFuncSetAttribute(flash_kernel<0>, cudaFuncAttributeMaxDynamicSharedMemorySize, FL_SMEM);
    cudaFuncSetAttribute(flash_kernel<1>, cudaFuncAttributeMaxDynamicSharedMemorySize, FL_SMEM);

    float *m, *xm, *h, *h2kv, *h2f, *q, *k, *v, *q2, *k2, *v2, *cat, *cat2, *O2p, *l2;
    cudaGetSymbolAddress((void**)&m,    g_m);
    cudaGetSymbolAddress((void**)&xm,   g_xm);
    cudaGetSymbolAddress((void**)&h,    g_h);
    cudaGetSymbolAddress((void**)&h2kv, g_h2kv);
    cudaGetSymbolAddress((void**)&h2f,  g_h2f);
    cudaGetSymbolAddress((void**)&q,    g_q);
    cudaGetSymbolAddress((void**)&k,    g_k);
    cudaGetSymbolAddress((void**)&v,    g_v);
    cudaGetSymbolAddress((void**)&q2,   g_q2);
    cudaGetSymbolAddress((void**)&k2,   g_k2);
    cudaGetSymbolAddress((void**)&v2,   g_v2);
    cudaGetSymbolAddress((void**)&cat,  g_cat);
    cudaGetSymbolAddress((void**)&cat2, g_cat2);
    cudaGetSymbolAddress((void**)&O2p,  g_O2p);
    cudaGetSymbolAddress((void**)&l2,   g_l2);

    mod_kernel<<<3 * HID, 256>>>(vec, mw, mb, m);

    // ================= Block 1 =================
    ln_mod_kernel<<<LX, 256>>>(x, xm, m);

    // qkv part of h   (M=4352, N=4608)
    tc_gemm2<0><<<dim3(QKVW / 256, LX / 256), 256, SMEM_G2>>>(
        xm, w1, h, HID, HID, HID, QKVW, b1, nullptr, 0, nullptr, LX);
    // mlp part -> gelu -> cat[:,HID:]   (M=4352, N=6144)
    tc_gemm2<2><<<dim3(MLP / 256, LX / 256), 256, SMEM_G2>>>(
        xm, w1 + (size_t)QKVW * HID, cat + HID, HID, HID, HID, CATW,
        b1 + QKVW, nullptr, 0, nullptr, LX);

    dim3 gqk(LX, NH);
    rmsrope_kernel<<<gqk, HD>>>(h + 0,       QKVW, pe, qs,      1, q, LX, 0, SOFT_SCALE);
    rmsrope_kernel<<<gqk, HD>>>(h + HID,     QKVW, pe, ks,      1, k, LX, 0, 1.f);
    rmsrope_kernel<<<gqk, HD>>>(h + 2 * HID, QKVW, pe, nullptr, 0, v, LX, 1, 1.f);

    // fused attention -> cat[:,0:HID]
    flash_kernel<0><<<dim3(LX / 128, NH), 256, FL_SMEM>>>(
        q, k, v, cat, nullptr,
        (size_t)LX * HD, (size_t)LX * HD, (size_t)HD * LX, LX,
        LX / 64, LX, CATW);

    // out_x = x + gate * (cat @ w2.T + b2)   (M=4352, N=1536)
    tc_gemm2<1><<<dim3(HID / 256, LX / 256), 256, SMEM_G2>>>(
        cat, w2, out, CATW, CATW, CATW, HID, b2, x, HID, m + 2 * HID, LX);

    // ================= Block 2 =================
    ln_mod_kernel<<<NC, 256>>>(cps, xm, m);
    ln_mod_kernel<<<4096, 256>>>(x + (size_t)256 * HID, xm + (size_t)NC * HID, m);

    // k,v cols for all rows   (M=4352, N=3072)
    tc_gemm2<0><<<dim3(3072 / 256, L2P / 256), 256, SMEM_G2>>>(
        xm, w1 + (size_t)HID * HID, h2kv, HID, HID, HID, 3072,
        b1 + HID, nullptr, 0, nullptr, L2P);
    // q cols for first 128 rows
    tc_gemm<256, 4, 0><<<dim3(HID / 256, 1, 1), 256, SM256>>>(
        xm, w1, h2f, HID, HID, HID, HID, 0, 0, 0, b1, nullptr, 0, nullptr, 128);
    // mlp cols (gelu) for first 128 rows -> cat2[:,HID:]
    tc_gemm<256, 4, 2><<<dim3(MLP / 256, 1, 1), 256, SM256>>>(
        xm, w1 + (size_t)QKVW * HID, cat2 + HID, HID, HID, HID, CATW,
        0, 0, 0, b1 + QKVW, nullptr, 0, nullptr, 128);

    dim3 gk2(L2V, NH);
    rmsrope_kernel<<<gk2, HD>>>(h2kv + 0,   3072, cpe, ks,      1, k2, L2P, 0, 1.f);
    rmsrope_kernel<<<gk2, HD>>>(h2kv + HID, 3072, cpe, nullptr, 0, v2, L2P, 1, 1.f);
    rmsrope_kernel<<<dim3(NC, NH), HD>>>(h2f, HID, cpe, qs, 1, q2, 128, 0, SOFT_SCALE);

    // split-K fused attention
    flash_kernel<1><<<dim3(NSPLIT, NH), 256, FL_SMEM>>>(
        q2, k2, v2, O2p, l2,
        (size_t)128 * HD, (size_t)L2P * HD, (size_t)HD * L2P, L2P,
        L2P / 64 / NSPLIT, L2V, 0);
    combine2_kernel<<<dim3(NC, NH), HD>>>(O2p, l2, cat2);

    // concepts_out = concepts + gate * (cat2 @ w2.T + b2)
    tc_gemm<256, 4, 1><<<dim3(HID / 256, 1, 1), 256, SM256>>>(
        cat2, w2, out + (size_t)LX * HID, CATW, CATW, CATW, HID,
        0, 0, 0, b2, cps, HID, m + 2 * HID, NC);
}

// round 13
// speedup vs baseline: 9.7820x; 1.1391x over previous
#include <cuda_runtime.h>
#include <cuda_bf16.h>
#include <cstdint>
#include <cstddef>

#define HID     1536
#define NH      12
#define HD      128
#define MLP     6144
#define LX      4352
#define NC      20
#define L2V     4116
#define L2P     4352
#define QKVW    4608
#define CATW    7680
#define NSPLIT  4
#define SOFT_SCALE 0.08838834764831845f

typedef unsigned int u32;
typedef unsigned long long u64;

#if defined(__CUDA_ARCH_FEAT_SM103_ALL) || defined(__CUDA_ARCH_FEAT_SM100_ALL) || defined(__CUDA_ARCH_FEAT_SM101_ALL)
#define HAS_TCGEN05 1
#else
#define HAS_TCGEN05 0
#endif

// ---------------- scratch ----------------
__device__ __align__(256) float g_m[3 * HID];
__device__ __align__(256) float g_xm[(size_t)LX * HID];
__device__ __align__(256) float g_xm2[(size_t)L2P * HID];
__device__ __align__(256) float g_h[(size_t)LX * QKVW];
__device__ __align__(256) float g_h2kv[(size_t)L2P * 3072];
__device__ __align__(256) float g_h2f[(size_t)128 * HID];
__device__ __align__(256) float g_q[(size_t)NH * LX * HD];
__device__ __align__(256) float g_k[(size_t)NH * LX * HD];
__device__ __align__(256) float g_v[(size_t)NH * HD * LX];      // vT [h][d][l]
__device__ __align__(256) float g_q2[(size_t)NH * 128 * HD];
__device__ __align__(256) float g_k2[(size_t)NH * L2P * HD];
__device__ __align__(256) float g_v2[(size_t)NH * HD * L2P];
__device__ __align__(256) float g_cat[(size_t)LX * CATW];
__device__ __align__(256) float g_cat2[(size_t)128 * CATW];
__device__ __align__(256) float g_O2p[(size_t)NSPLIT * NH * 128 * HD];
__device__ __align__(256) float g_l2[(size_t)NSPLIT * NH * 128];

// ---------------- PTX helpers ----------------
__device__ __forceinline__ u32 s2u(const void* p) { return (u32)__cvta_generic_to_shared(p); }
__device__ __forceinline__ u32 swz(u32 o) { return o ^ ((o >> 3) & 0x70); }
__device__ __forceinline__ void cp16(u32 dst, const void* src) {
    asm volatile("cp.async.cg.shared.global [%0], [%1], 16;" :: "r"(dst), "l"(src));
}
__device__ __forceinline__ void cp_commit() { asm volatile("cp.async.commit_group;" ::: "memory"); }
template <int N> __device__ __forceinline__ void cp_wait() {
    asm volatile("cp.async.wait_group %0;" :: "n"(N) : "memory");
}
__device__ __forceinline__ bool elect1() {
    u32 p;
    asm volatile("{\n\t.reg .pred p;\n\telect.sync _|p, 0xFFFFFFFF;\n\tselp.b32 %0,1,0,p;\n\t}" : "=r"(p));
    return p != 0;
}
__device__ __forceinline__ u64 sdesc(u32 addr) {
    return 0x4000404000010000ull | (u64)((addr >> 4) & 0x3FFF);
}
__device__ __forceinline__ void mbar_init(u32 a) {
    u32 one = 1;
    asm volatile("mbarrier.init.shared.b64 [%0], %1;" :: "r"(a), "r"(one) : "memory");
}
__device__ __forceinline__ void mbar_wait(u32 a, u32 parity) {
    asm volatile(
        "{\n\t.reg .pred P;\n"
        "LW_%=:\n\t"
        "mbarrier.try_wait.parity.acquire.cta.shared::cta.b64 P, [%0], %1, 0x989680;\n\t"
        "@P bra LD_%=;\n\t"
        "bra LW_%=;\n"
        "LD_%=:\n\t}" :: "r"(a), "r"(parity) : "memory");
}
__device__ __forceinline__ void fence_async_shared() {
    asm volatile("fence.proxy.async.shared::cta;" ::: "memory");
}
__device__ __forceinline__ void tc_commit(u32 mbar) {
#if HAS_TCGEN05
    asm volatile("tcgen05.commit.cta_group::1.mbarrier::arrive::one.shared::cluster.b64 [%0];"
                 :: "r"(mbar) : "memory");
#else
    (void)mbar;
#endif
}
__device__ __forceinline__ void mma_tf32(u32 d, u64 ad, u64 bd, u32 idesc, u32 en) {
#if HAS_TCGEN05
    asm volatile(
        "{\n\t.reg .pred p;\n\tsetp.ne.u32 p, %4, 0;\n\t"
        "tcgen05.mma.cta_group::1.kind::tf32 [%0], %1, %2, %3, {%5,%5,%5,%5}, p;\n\t}"
        :: "r"(d), "l"(ad), "l"(bd), "r"(idesc), "r"(en), "r"(0u) : "memory");
#else
    (void)d; (void)ad; (void)bd; (void)idesc; (void)en;
#endif
}
__device__ __forceinline__ void tc_fence_after() {
#if HAS_TCGEN05
    asm volatile("tcgen05.fence::after_thread_sync;" ::: "memory");
#endif
}
__device__ __forceinline__ void tc_fence_before() {
#if HAS_TCGEN05
    asm volatile("tcgen05.fence::before_thread_sync;" ::: "memory");
#endif
}
__device__ __forceinline__ void tmem_alloc(u32 dst_smem, u32 ncols) {
#if HAS_TCGEN05
    asm volatile("tcgen05.alloc.cta_group::1.sync.aligned.shared::cta.b32 [%0], %1;"
                 :: "r"(dst_smem), "r"(ncols) : "memory");
#else
    (void)dst_smem; (void)ncols;
#endif
}
__device__ __forceinline__ void tmem_relinquish() {
#if HAS_TCGEN05
    asm volatile("tcgen05.relinquish_alloc_permit.cta_group::1.sync.aligned;");
#endif
}
__device__ __forceinline__ void tmem_dealloc(u32 tmem, u32 ncols) {
#if HAS_TCGEN05
    asm volatile("tcgen05.dealloc.cta_group::1.sync.aligned.b32 %0, %1;" :: "r"(tmem), "r"(ncols));
#else
    (void)tmem; (void)ncols;
#endif
}
__device__ __forceinline__ void tmem_wait_ld() {
#if HAS_TCGEN05
    asm volatile("tcgen05.wait::ld.sync.aligned;" ::: "memory");
#endif
}
__device__ __forceinline__ void ldtm32(u32* r, u32 a) {
#if HAS_TCGEN05
    asm volatile(
        "tcgen05.ld.sync.aligned.32x32b.x32.b32 "
        "{%0, %1, %2, %3, %4, %5, %6, %7, "
        " %8, %9, %10, %11, %12, %13, %14, %15, "
        " %16, %17, %18, %19, %20, %21, %22, %23, "
        " %24, %25, %26, %27, %28, %29, %30, %31}, [%32];"
        : "=r"(r[0]),  "=r"(r[1]),  "=r"(r[2]),  "=r"(r[3]),
          "=r"(r[4]),  "=r"(r[5]),  "=r"(r[6]),  "=r"(r[7]),
          "=r"(r[8]),  "=r"(r[9]),  "=r"(r[10]), "=r"(r[11]),
          "=r"(r[12]), "=r"(r[13]), "=r"(r[14]), "=r"(r[15]),
          "=r"(r[16]), "=r"(r[17]), "=r"(r[18]), "=r"(r[19]),
          "=r"(r[20]), "=r"(r[21]), "=r"(r[22]), "=r"(r[23]),
          "=r"(r[24]), "=r"(r[25]), "=r"(r[26]), "=r"(r[27]),
          "=r"(r[28]), "=r"(r[29]), "=r"(r[30]), "=r"(r[31])
        : "r"(a));
#else
#pragma unroll
    for (int i = 0; i < 32; ++i) r[i] = 0u;
    (void)a;
#endif
}
__device__ __forceinline__ float gelu_f(float x) {
    float u = 0.7978845608028654f * (x + 0.044715f * x * x * x);
    return 0.5f * x * (1.f + tanhf(u));
}

// ---------------------------------------------------------------------------
// 256x256 tf32 GEMM core pieces (identical mainloop to round-8 tc_gemm2)
// ---------------------------------------------------------------------------
#define G2_STAGES 3
#define G2_STRIDE 65536
#define SMEM_G2 (1024 + G2_STAGES * G2_STRIDE)
#define G2_IDESC ((1u << 4) | (2u << 7) | (2u << 10) | (32u << 17) | (8u << 24))

#define G2_LOAD(pp, st)                                                        \
    do {                                                                       \
        _Pragma("unroll")                                                      \
        for (int i = 0; i < 8; ++i) {      /* A: 256 rows x 128B */            \
            int o = tid + (i << 8);                                            \
            int r_ = o >> 3, c_ = o & 7;                                       \
            cp16((st) + ((u32)(r_ >> 7) << 14) +                               \
                     swz((u32)(((r_ & 127) << 7) + (c_ << 4))),                \
                 A + (size_t)(bm + r_) * lda + ((pp) << 5) + (c_ << 2));       \
        }                                                                      \
        _Pragma("unroll")                                                      \
        for (int i = 0; i < 8; ++i) {      /* B: 256 rows x 128B */            \
            int o = tid + (i << 8);                                            \
            int r_ = o >> 3, c_ = o & 7;                                       \
            cp16((st) + 32768u + swz((u32)((r_ << 7) + (c_ << 4))),            \
                 B + (size_t)(bn + r_) * ldb + ((pp) << 5) + (c_ << 2));       \
        }                                                                      \
    } while (0)

// Mainloop + epilogue as a device function. epi: 0 bias, 1 res+gate, 2 gelu.
__device__ __forceinline__ void gemm2_body(
    const float* __restrict__ A, const float* __restrict__ B, float* __restrict__ C,
    int K, int lda, int ldb, int ldc, int bm, int bn,
    const float* __restrict__ bias, const float* __restrict__ res, int ldres,
    const float* __restrict__ gate, int Mstore, int epi,
    u32 sb, int tid)
{
    const u32 mb0 = sb + 8;
    const u32 tile0 = sb + 1024;

    if (tid == 0)
        for (int s = 0; s < G2_STAGES; ++s) mbar_init(mb0 + 8 * s);
    if (tid < 32) { tmem_alloc(sb, 512); tmem_relinquish(); }
    __syncthreads();
    u32 tmem;
    asm volatile("ld.shared.b32 %0, [%1];" : "=r"(tmem) : "r"(sb));

    const int nk = K >> 5;

    for (int p = 0; p < G2_STAGES - 1; ++p) {
        if (p < nk) G2_LOAD(p, tile0 + (u32)p * G2_STRIDE);
        cp_commit();
    }

    for (int it = 0; it < nk; ++it) {
        const int b = it % G2_STAGES;
        cp_wait<G2_STAGES - 2>();
        fence_async_shared();
        __syncthreads();

        if (tid < 32 && elect1()) {
            u64 da0 = sdesc(tile0 + (u32)b * G2_STRIDE);
            u64 da1 = sdesc(tile0 + (u32)b * G2_STRIDE + 16384u);
            u64 db  = sdesc(tile0 + (u32)b * G2_STRIDE + 32768u);
#pragma unroll
            for (int j = 0; j < 4; ++j) {
                u32 en = (u32)((it > 0) || (j > 0));
                mma_tf32(tmem,       da0 + j * 2, db + j * 2, G2_IDESC, en);
                mma_tf32(tmem + 256, da1 + j * 2, db + j * 2, G2_IDESC, en);
            }
            tc_commit(mb0 + 8 * b);
        }

        const int p = it + G2_STAGES - 1;
        if (p < nk) {
            if (it >= 1)
                mbar_wait(mb0 + 8 * (p % G2_STAGES), (u32)(((it - 1) / G2_STAGES) & 1));
            G2_LOAD(p, tile0 + (u32)(p % G2_STAGES) * G2_STRIDE);
        }
        cp_commit();
    }

    mbar_wait(mb0 + 8 * ((nk - 1) % G2_STAGES), (u32)(((nk - 1) / G2_STAGES) & 1));
    tc_fence_after();

    {
        const int w = tid >> 5, lane = tid & 31;
        const int accsel = w >> 2;
        const int row = bm + accsel * 128 + (w & 3) * 32 + lane;
        const bool doSt = row < Mstore;
        float* crow = C + (size_t)row * ldc;
        const float* rrow = (epi == 1 && doSt) ? (res + (size_t)row * ldres) : nullptr;
        const u32 tbase = tmem + (u32)accsel * 256;
#pragma unroll
        for (int g = 0; g < 8; ++g) {
            u32 regs[32];
            ldtm32(regs, tbase + g * 32);
            tmem_wait_ld();
            if (doSt) {
#pragma unroll
                for (int q4 = 0; q4 < 8; ++q4) {
                    int col = bn + g * 32 + q4 * 4;
                    float4 vv;
                    vv.x = __uint_as_float(regs[q4 * 4 + 0]);
                    vv.y = __uint_as_float(regs[q4 * 4 + 1]);
                    vv.z = __uint_as_float(regs[q4 * 4 + 2]);
                    vv.w = __uint_as_float(regs[q4 * 4 + 3]);
                    if (bias) {
                        float4 bb = *(const float4*)(bias + col);
                        vv.x += bb.x; vv.y += bb.y; vv.z += bb.z; vv.w += bb.w;
                    }
                    if (epi == 1) {
                        float4 rr = *(const float4*)(rrow + col);
                        float4 gg = *(const float4*)(gate + col);
                        vv.x = rr.x + gg.x * vv.x; vv.y = rr.y + gg.y * vv.y;
                        vv.z = rr.z + gg.z * vv.z; vv.w = rr.w + gg.w * vv.w;
                    } else if (epi == 2) {
                        vv.x = gelu_f(vv.x); vv.y = gelu_f(vv.y);
                        vv.z = gelu_f(vv.z); vv.w = gelu_f(vv.w);
                    }
                    *(float4*)(crow + col) = vv;
                }
            }
        }
    }
    __syncthreads();
    if (tid < 32) tmem_dealloc(tmem, 512);
}

// Merged launch: qkv1 (18 Ntiles) | mlp1-gelu (24) | kv2 (12), all M=4352/K=1536.
__global__ __launch_bounds__(256, 1)
void tc_gemm_merged(const float* __restrict__ xm, const float* __restrict__ xm2,
                    const float* __restrict__ w1,
                    float* __restrict__ h, float* __restrict__ catm,
                    float* __restrict__ h2kv, const float* __restrict__ b1)
{
    extern __shared__ char smem[];
    const u32 sb = s2u(smem);
    const int tid = threadIdx.x;

    int idx = blockIdx.x;
    const float* A; const float* B; float* C; const float* bs;
    int ldc, epi, mstore, ntil;
    if (idx < 18 * 17) {
        A = xm;  B = w1;                        C = h;    bs = b1;
        ldc = QKVW; epi = 0; mstore = LX;  ntil = 18;
    } else if (idx < 18 * 17 + 24 * 17) {
        idx -= 18 * 17;
        A = xm;  B = w1 + (size_t)QKVW * HID;   C = catm; bs = b1 + QKVW;
        ldc = CATW; epi = 2; mstore = LX;  ntil = 24;
    } else {
        idx -= 18 * 17 + 24 * 17;
        A = xm2; B = w1 + (size_t)HID * HID;    C = h2kv; bs = b1 + HID;
        ldc = 3072; epi = 0; mstore = L2V; ntil = 12;
    }
    const int bn = (idx % ntil) * 256;
    const int bm = (idx / ntil) * 256;

    gemm2_body(A, B, C, HID, HID, HID, ldc, bm, bn, bs, nullptr, 0, nullptr,
               mstore, epi, sb, tid);
}

// Standalone 256x256 GEMM (used for out1, EPI=1)
template <int EPI>
__global__ __launch_bounds__(256, 1)
void tc_gemm2(const float* __restrict__ A, const float* __restrict__ B, float* __restrict__ C,
              int K, int lda, int ldb, int ldc,
              const float* __restrict__ bias,
              const float* __restrict__ res, int ldres,
              const float* __restrict__ gate, int Mstore)
{
    extern __shared__ char smem[];
    gemm2_body(A, B, C, K, lda, ldb, ldc, blockIdx.y * 256, blockIdx.x * 256,
               bias, res, ldres, gate, Mstore, EPI, s2u(smem), threadIdx.x);
}

// ---------------------------------------------------------------------------
// tc_gemm: original 128 x BN tile (kept for M=128 block-2 GEMMs)
// ---------------------------------------------------------------------------
template <int BN>
__device__ __forceinline__ void load_chunk(u32 st, const float* A, const float* B,
                                           int bm, int bn, int kt, int lda, int ldb, int tid)
{
#pragma unroll
    for (int i = 0; i < 4; ++i) {
        int o = tid + (i << 8);
        int r = o >> 3, c = o & 7;
        cp16(st + swz((u32)((r << 7) + (c << 4))),
             A + (size_t)(bm + r) * lda + kt + (c << 2));
    }
    const u32 stB = st + 128 * 128;
#pragma unroll
    for (int i = 0; i < BN / 32; ++i) {
        int o = tid + (i << 8);
        int r = o >> 3, c = o & 7;
        cp16(stB + swz((u32)((r << 7) + (c << 4))),
             B + (size_t)(bn + r) * ldb + kt + (c << 2));
    }
}

template <int BN, int STAGES, int EPI>
__global__ __launch_bounds__(256, 1)
void tc_gemm(const float* __restrict__ A, const float* __restrict__ B, float* __restrict__ C,
             int K, int lda, int ldb, int ldc,
             size_t sA, size_t sB, size_t sC,
             const float* __restrict__ bias,
             const float* __restrict__ res, int ldres,
             const float* __restrict__ gate, int Mstore)
{
    constexpr int ASZ = 128 * 128;
    constexpr int STRIDE = ASZ + BN * 128;
    constexpr u32 IDESC = (1u << 4) | (2u << 7) | (2u << 10) |
                          ((u32)(BN / 8) << 17) | (8u << 24);

    extern __shared__ char smem[];
    const u32 sb = s2u(smem);
    const u32 mb0 = sb + 8;
    const u32 tile0 = sb + 1024;

    A += (size_t)blockIdx.z * sA;
    B += (size_t)blockIdx.z * sB;
    C += (size_t)blockIdx.z * sC;
    const int bm = blockIdx.y * 128;
    const int bn = blockIdx.x * BN;
    const int tid = threadIdx.x;

    if (tid == 0)
        for (int s = 0; s < STAGES; ++s) mbar_init(mb0 + 8 * s);
    if (tid < 32) { tmem_alloc(sb, BN); tmem_relinquish(); }
    __syncthreads();
    u32 tmem;
    asm volatile("ld.shared.b32 %0, [%1];" : "=r"(tmem) : "r"(sb));

    const int nk = K >> 5;
    for (int p = 0; p < STAGES - 1; ++p) {
        if (p < nk)
            load_chunk<BN>(tile0 + (p % STAGES) * STRIDE, A, B, bm, bn, p << 5, lda, ldb, tid);
        cp_commit();
    }

    for (int it = 0; it < nk; ++it) {
        const int b = it % STAGES;
        cp_wait<STAGES - 2>();
        fence_async_shared();
        __syncthreads();

        if (tid < 32) {
            u64 da = sdesc(tile0 + b * STRIDE);
            u64 db = sdesc(tile0 + b * STRIDE + ASZ);
            if (elect1()) {
#pragma unroll
                for (int j = 0; j < 4; ++j)
                    mma_tf32(tmem, da + j * 2, db + j * 2, IDESC, (u32)((it > 0) || (j > 0)));
                tc_commit(mb0 + 8 * b);
            }
        }
        const int p = it + STAGES - 1;
        if (p < nk) {
            if (it >= 1)
                mbar_wait(mb0 + 8 * (p % STAGES), (u32)(((it - 1) / STAGES) & 1));
            load_chunk<BN>(tile0 + (p % STAGES) * STRIDE, A, B, bm, bn, p << 5, lda, ldb, tid);
        }
        cp_commit();
    }

    mbar_wait(mb0 + 8 * ((nk - 1) % STAGES), (u32)(((nk - 1) / STAGES) & 1));
    tc_fence_after();

    if (tid < 128) {
        const int w = tid >> 5, lane = tid & 31;
        const int row = bm + w * 32 + lane;
        const bool doSt = row < Mstore;
        float* crow = C + (size_t)row * ldc;
        const float* rrow = (EPI == 1 && doSt) ? (res + (size_t)row * ldres) : nullptr;
#pragma unroll
        for (int g = 0; g < BN / 32; ++g) {
            u32 regs[32];
            ldtm32(regs, tmem + g * 32);
            tmem_wait_ld();
            if (doSt) {
#pragma unroll
                for (int q4 = 0; q4 < 8; ++q4) {
                    int col = bn + g * 32 + q4 * 4;
                    float4 vv;
                    vv.x = __uint_as_float(regs[q4 * 4 + 0]);
                    vv.y = __uint_as_float(regs[q4 * 4 + 1]);
                    vv.z = __uint_as_float(regs[q4 * 4 + 2]);
                    vv.w = __uint_as_float(regs[q4 * 4 + 3]);
                    if (bias) {
                        float4 bb = *(const float4*)(bias + col);
                        vv.x += bb.x; vv.y += bb.y; vv.z += bb.z; vv.w += bb.w;
                    }
                    if (EPI == 1) {
                        float4 rr = *(const float4*)(rrow + col);
                        float4 gg = *(const float4*)(gate + col);
                        vv.x = rr.x + gg.x * vv.x; vv.y = rr.y + gg.y * vv.y;
                        vv.z = rr.z + gg.z * vv.z; vv.w = rr.w + gg.w * vv.w;
                    } else if (EPI == 2) {
                        vv.x = gelu_f(vv.x); vv.y = gelu_f(vv.y);
                        vv.z = gelu_f(vv.z); vv.w = gelu_f(vv.w);
                    }
                    *(float4*)(crow + col) = vv;
                }
            }
        }
    }
    __syncthreads();
    if (tid < 32) tmem_dealloc(tmem, BN);
}

// ---------------- flash attention (unchanged) ----------------
__device__ __forceinline__ void ld_ktile(u32 dstb, const float* Kb, int jt, int tid) {
#pragma unroll
    for (int i = 0; i < 8; ++i) {
        int o = tid + (i << 8);
        int row = o >> 5, inner = o & 31, c = inner >> 3, s = inner & 7;
        cp16(dstb + c * 8192 + swz((u32)((row << 7) + (s << 4))),
             Kb + (size_t)(jt * 64 + row) * HD + (c << 5) + (s << 2));
    }
}
__device__ __forceinline__ void ld_vtile(u32 dstb, const float* Vb, int jt, int vLD, int tid) {
#pragma unroll
    for (int i = 0; i < 8; ++i) {
        int o = tid + (i << 8);
        int row = o >> 4, inner = o & 15, c = inner >> 3, s = inner & 7;
        cp16(dstb + c * 16384 + swz((u32)((row << 7) + (s << 4))),
             Vb + (size_t)row * vLD + jt * 64 + (c << 5) + (s << 2));
    }
}
#define IDESC_QK ((1u << 4) | (2u << 7) | (2u << 10) | (8u << 17) | (8u << 24))
#define IDESC_PV ((1u << 4) | (2u << 7) | (2u << 10) | (16u << 17) | (8u << 24))

__device__ __forceinline__ void issue_qk(u32 dcol, u32 sQ, u32 sKb) {
#pragma unroll
    for (int c = 0; c < 4; ++c) {
        u64 da = sdesc(sQ + c * 16384);
        u64 db = sdesc(sKb + c * 8192);
#pragma unroll
        for (int j = 0; j < 4; ++j)
            mma_tf32(dcol, da + j * 2, db + j * 2, IDESC_QK, (u32)((c | j) != 0));
    }
}
__device__ __forceinline__ void issue_pv(u32 dcol, u32 sPb, u32 sVb, bool first) {
#pragma unroll
    for (int c = 0; c < 2; ++c) {
        u64 da = sdesc(sPb + c * 16384);
        u64 db = sdesc(sVb + c * 16384);
#pragma unroll
        for (int j = 0; j < 4; ++j)
            mma_tf32(dcol, da + j * 2, db + j * 2, IDESC_PV,
                     (u32)(!(first && c == 0 && j == 0)));
    }
}

#define FL_SMEM (2048 + 65536 + 65536 + 65536 + 32768)

template <int SPLITOUT>
__global__ __launch_bounds__(256, 1)
void flash_kernel(const float* __restrict__ Qg, const float* __restrict__ Kg,
                  const float* __restrict__ Vg,
                  float* __restrict__ dst, float* __restrict__ lout,
                  size_t qHS, size_t kHS, size_t vHS, int vLD,
                  int nt, int nvalid, int ldd)
{
    extern __shared__ char smem[];
    float* rowsum = (float*)(smem + 16);
    const u32 sb = s2u(smem);
    const u32 mbar = sb + 8;
    const u32 sQ = sb + 2048;
    const u32 sK = sQ + 65536;
    const u32 sV = sK + 65536;
    const u32 sP = sV + 65536;

    const int h = blockIdx.y;
    const int tid = threadIdx.x;
    const int wid = tid >> 5, lane = tid & 31;
    const int hf = wid >> 2;
    const int r = ((wid & 3) << 5) + lane;
    const int t0 = SPLITOUT ? blockIdx.x * nt : 0;
    const int bm = SPLITOUT ? 0 : blockIdx.x * 128;

    const float* Qb = Qg + (size_t)h * qHS + (size_t)bm * HD;
    const float* Kb = Kg + (size_t)h * kHS;
    const float* Vb = Vg + (size_t)h * vHS;

#pragma unroll
    for (int i = 0; i < 16; ++i) {
        int o = tid + (i << 8);
        int row = o >> 5, inner = o & 31, c = inner >> 3, s = inner & 7;
        cp16(sQ + c * 16384 + swz((u32)((row << 7) + (s << 4))),
             Qb + (size_t)row * HD + (c << 5) + (s << 2));
    }
    ld_ktile(sK, Kb, t0, tid);
    ld_vtile(sV, Vb, t0, vLD, tid);
    cp_commit();
    if (nt > 1) ld_ktile(sK + 32768, Kb, t0 + 1, tid);
    cp_commit();

    if (tid == 0) mbar_init(mbar);
    if (tid < 32) { tmem_alloc(sb, 256); tmem_relinquish(); }
    __syncthreads();
    u32 tmem;
    asm volatile("ld.shared.b32 %0, [%1];" : "=r"(tmem) : "r"(sb));
    const u32 tO = tmem;

    cp_wait<1>();
    fence_async_shared();
    __syncthreads();
    if (tid < 32 && elect1()) {
        issue_qk(tmem + 128, sQ, sK);
        tc_commit(mbar);
    }

    float lacc = 0.f;
    u32 par = 0;

    for (int t = 0; t < nt; ++t) {
        const u32 scol = 128 + ((u32)(t & 1) << 6);

        mbar_wait(mbar, par); par ^= 1;
        tc_fence_after();
        cp_wait<0>();
        fence_async_shared();
        __syncthreads();

        if (tid < 32 && elect1()) {
            if (t + 1 < nt)
                issue_qk(tmem + 128 + ((u32)((t + 1) & 1) << 6),
                         sQ, sK + ((u32)((t + 1) & 1) * 32768u));
        }
        if (t + 2 < nt) ld_ktile(sK + ((u32)(t & 1) * 32768u), Kb, t0 + t + 2, tid);
        if (t + 1 < nt) ld_vtile(sV + ((u32)((t + 1) & 1) * 32768u), Vb, t0 + t + 1, vLD, tid);
        cp_commit();

        u32 sr[32];
        ldtm32(sr, tmem + scol + ((u32)hf << 5));
        tmem_wait_ld();
        float p[32];
        float ls = 0.f;
        const int jb = (t0 + t) * 64 + (hf << 5);
#pragma unroll
        for (int i = 0; i < 32; ++i) {
            float sv = __uint_as_float(sr[i]);
            float e = (jb + i < nvalid) ? __expf(sv) : 0.f;
            p[i] = e; ls += e;
        }
        lacc += ls;

        const u32 pbase = sP + (hf ? 16384u : 0u);
#pragma unroll
        for (int g = 0; g < 8; ++g) {
            u32 addr = pbase + swz(((u32)r << 7) + ((u32)g << 4));
            asm volatile("st.shared.v4.b32 [%0], {%1,%2,%3,%4};" :: "r"(addr),
                "r"(__float_as_uint(p[4 * g + 0])), "r"(__float_as_uint(p[4 * g + 1])),
                "r"(__float_as_uint(p[4 * g + 2])), "r"(__float_as_uint(p[4 * g + 3]))
                : "memory");
        }
        tc_fence_before();
        fence_async_shared();
        __syncthreads();

        if (tid < 32 && elect1()) {
            tc_fence_after();
            issue_pv(tO, sP, sV + ((u32)(t & 1) * 32768u), t == 0);
            tc_commit(mbar);
        }
    }

    mbar_wait(mbar, par);
    tc_fence_after();

    rowsum[r * 2 + hf] = lacc;
    __syncthreads();
    const float ltot = rowsum[r * 2] + rowsum[r * 2 + 1];

    if (SPLITOUT) {
        float* od = dst + (((size_t)blockIdx.x * NH + h) * 128 + r) * HD + (hf << 6);
#pragma unroll
        for (int g2 = 0; g2 < 2; ++g2) {
            u32 orgs[32];
            ldtm32(orgs, tO + ((u32)hf << 6) + ((u32)g2 << 5));
            tmem_wait_ld();
#pragma unroll
            for (int i = 0; i < 8; ++i) {
                float4 vv;
                vv.x = __uint_as_float(orgs[i * 4 + 0]);
                vv.y = __uint_as_float(orgs[i * 4 + 1]);
                vv.z = __uint_as_float(orgs[i * 4 + 2]);
                vv.w = __uint_as_float(orgs[i * 4 + 3]);
                *(float4*)(od + (g2 << 5) + i * 4) = vv;
            }
        }
        if (hf == 0)
            lout[((size_t)blockIdx.x * NH + h) * 128 + r] = ltot;
    } else {
        const float inv = 1.f / ltot;
        float* od = dst + (size_t)(bm + r) * ldd + h * HD + (hf << 6);
#pragma unroll
        for (int g2 = 0; g2 < 2; ++g2) {
            u32 orgs[32];
            ldtm32(orgs, tO + ((u32)hf << 6) + ((u32)g2 << 5));
            tmem_wait_ld();
#pragma unroll
            for (int i = 0; i < 8; ++i) {
                float4 vv;
                vv.x = __uint_as_float(orgs[i * 4 + 0]) * inv;
                vv.y = __uint_as_float(orgs[i * 4 + 1]) * inv;
                vv.z = __uint_as_float(orgs[i * 4 + 2]) * inv;
                vv.w = __uint_as_float(orgs[i * 4 + 3]) * inv;
                *(float4*)(od + (g2 << 5) + i * 4) = vv;
            }
        }
    }
    tc_fence_before();
    __syncthreads();
    if (tid < 32) tmem_dealloc(tmem, 256);
}

__global__ void combine2_kernel(const float* __restrict__ Op, const float* __restrict__ lp,
                                float* __restrict__ cat2)
{
    int r = blockIdx.x, h = blockIdx.y, d = threadIdx.x;
    float o = 0.f, l = 0.f;
#pragma unroll
    for (int s = 0; s < NSPLIT; ++s) {
        o += Op[(((size_t)s * NH + h) * 128 + r) * HD + d];
        l += lp[((size_t)s * NH + h) * 128 + r];
    }
    cat2[(size_t)r * CATW + h * HD + d] = o / l;
}

// ---------------- small elementwise kernels ----------------
__global__ void mod_kernel(const float* __restrict__ vec, const float* __restrict__ mw,
                           const float* __restrict__ mb, float* __restrict__ m)
{
    int o = blockIdx.x, t = threadIdx.x;
    float s = 0.f;
    for (int k = t; k < HID; k += 256) {
        float v = vec[k];
        s += (v / (1.f + expf(-v))) * mw[(size_t)o * HID + k];
    }
    __shared__ float red[256];
    red[t] = s; __syncthreads();
    for (int st = 128; st > 0; st >>= 1) { if (t < st) red[t] += red[t + st]; __syncthreads(); }
    if (t == 0) m[o] = red[0] + mb[o];
}

// 384 threads; one float4 per thread kept in registers.
__global__ void ln_mod_kernel(const float* __restrict__ in, float* __restrict__ out,
                              const float* __restrict__ m)
{
    const int row = blockIdx.x, t = threadIdx.x;
    __shared__ float red[16];

    float4 xv = ((const float4*)(in + (size_t)row * HID))[t];

    float s = xv.x + xv.y + xv.z + xv.w;
#pragma unroll
    for (int o = 16; o; o >>= 1) s += __shfl_xor_sync(0xffffffffu, s, o);
    if ((t & 31) == 0) red[t >> 5] = s;
    __syncthreads();
    if (t < 32) {
        float v = (t < 12) ? red[t] : 0.f;
#pragma unroll
        for (int o = 8; o; o >>= 1) v += __shfl_xor_sync(0xffffffffu, v, o);
        if (t == 0) red[12] = v;
    }
    __syncthreads();
    const float mu = red[12] * (1.f / HID);
    __syncthreads();

    float4 d;
    d.x = xv.x - mu; d.y = xv.y - mu; d.z = xv.z - mu; d.w = xv.w - mu;
    float ss = d.x * d.x + d.y * d.y + d.z * d.z + d.w * d.w;
#pragma unroll
    for (int o = 16; o; o >>= 1) ss += __shfl_xor_sync(0xffffffffu, ss, o);
    if ((t & 31) == 0) red[t >> 5] = ss;
    __syncthreads();
    if (t < 32) {
        float v = (t < 12) ? red[t] : 0.f;
#pragma unroll
        for (int o = 8; o; o >>= 1) v += __shfl_xor_sync(0xffffffffu, v, o);
        if (t == 0) red[13] = v;
    }
    __syncthreads();
    const float inv = rsqrtf(red[13] * (1.f / HID) + 1e-6f);

    float4 sc = ((const float4*)(m + HID))[t];
    float4 sh = ((const float4*)m)[t];
    float4 ov;
    ov.x = (1.f + sc.x) * (d.x * inv) + sh.x;
    ov.y = (1.f + sc.y) * (d.y * inv) + sh.y;
    ov.z = (1.f + sc.z) * (d.z * inv) + sh.z;
    ov.w = (1.f + sc.w) * (d.w * inv) + sh.w;
    ((float4*)(out + (size_t)row * HID))[t] = ov;
}

// rmsnorm + rope; coalesced head-major output (no transpose path).
__global__ void rmsrope_kernel(const float* __restrict__ src, int ldh,
                               const float* __restrict__ pe,
                               const float* __restrict__ scale,
                               float* __restrict__ dst, int dstL, float premul)
{
    int l = blockIdx.x, hd = blockIdx.y, d = threadIdx.x;
    float v = src[(size_t)l * ldh + hd * HD + d];
    __shared__ float sv[HD];
    __shared__ float wred[4];

    float ss = v * v;
#pragma unroll
    for (int o = 16; o > 0; o >>= 1) ss += __shfl_xor_sync(0xffffffffu, ss, o);
    if ((d & 31) == 0) wred[d >> 5] = ss;
    __syncthreads();
    float tot = wred[0] + wred[1] + wred[2] + wred[3];
    v = v * rsqrtf(tot * (1.f / HD) + 1e-6f) * scale[d] * premul;
    __syncthreads();

    sv[d] = v; __syncthreads();
    int i = d >> 1, j = d & 1;
    const float* pp = pe + (size_t)l * 256 + i * 4 + j * 2;
    float outv = pp[0] * sv[2 * i] + pp[1] * sv[2 * i + 1];

    dst[((size_t)hd * dstL + l) * HD + d] = outv;
}

// Coalesced 32x32 tiled transpose: v[hd][d][l] <- src[l][hd*HD+d]
__global__ void transpose_v(const float* __restrict__ src, int ldh,
                            float* __restrict__ dst, int dstL, int nrows)
{
    __shared__ float s[32][33];
    const int l0 = blockIdx.x * 32, d0 = blockIdx.y * 32, hd = blockIdx.z;
    const int tx = threadIdx.x, ty = threadIdx.y;
#pragma unroll
    for (int i = 0; i < 4; ++i) {
        int l = l0 + ty + i * 8;
        if (l < nrows)
            s[ty + i * 8][tx] = src[(size_t)l * ldh + hd * HD + d0 + tx];
    }
    __syncthreads();
#pragma unroll
    for (int i = 0; i < 4; ++i) {
        int d = d0 + ty + i * 8;
        int l = l0 + tx;
        if (l < nrows)
            dst[((size_t)hd * HD + d) * dstL + l] = s[tx][ty + i * 8];
    }
}

// ---------------- launch ----------------
#define SMEM_FOR(BN, S) (1024 + (S) * ((128 * 128) + (BN) * 128))

extern "C" void kernel_launch(void* const* d_in, const int* in_sizes, int n_in,
                              void* d_out, int out_size)
{
    (void)in_sizes; (void)n_in; (void)out_size;
    const float* x   = (const float*)d_in[0];
    const float* cps = (const float*)d_in[1];
    const float* vec = (const float*)d_in[2];
    const float* pe  = (const float*)d_in[3];
    const float* cpe = (const float*)d_in[4];
    const float* w1  = (const float*)d_in[5];
    const float* b1  = (const float*)d_in[6];
    const float* w2  = (const float*)d_in[7];
    const float* b2  = (const float*)d_in[8];
    const float* qs  = (const float*)d_in[9];
    const float* ks  = (const float*)d_in[10];
    const float* mw  = (const float*)d_in[11];
    const float* mb  = (const float*)d_in[12];
    float* out = (float*)d_out;

    const int SM256 = SMEM_FOR(256, 4);
    cudaFuncSetAttribute(tc_gemm<256, 4, 0>, cudaFuncAttributeMaxDynamicSharedMemorySize, SM256);
    cudaFuncSetAttribute(tc_gemm<256, 4, 1>, cudaFuncAttributeMaxDynamicSharedMemorySize, SM256);
    cudaFuncSetAttribute(tc_gemm<256, 4, 2>, cudaFuncAttributeMaxDynamicSharedMemorySize, SM256);
    cudaFuncSetAttribute(tc_gemm_merged, cudaFuncAttributeMaxDynamicSharedMemorySize, SMEM_G2);
    cudaFuncSetAttribute(tc_gemm2<1>, cudaFuncAttributeMaxDynamicSharedMemorySize, SMEM_G2);
    cudaFuncSetAttribute(flash_kernel<0>, cudaFuncAttributeMaxDynamicSharedMemorySize, FL_SMEM);
    cudaFuncSetAttribute(flash_kernel<1>, cudaFuncAttributeMaxDynamicSharedMemorySize, FL_SMEM);

    float *m, *xm, *xm2, *h, *h2kv, *h2f, *q, *k, *v, *q2, *k2, *v2, *cat, *cat2, *O2p, *l2;
    cudaGetSymbolAddress((void**)&m,    g_m);
    cudaGetSymbolAddress((void**)&xm,   g_xm);
    cudaGetSymbolAddress((void**)&xm2,  g_xm2);
    cudaGetSymbolAddress((void**)&h,    g_h);
    cudaGetSymbolAddress((void**)&h2kv, g_h2kv);
    cudaGetSymbolAddress((void**)&h2f,  g_h2f);
    cudaGetSymbolAddress((void**)&q,    g_q);
    cudaGetSymbolAddress((void**)&k,    g_k);
    cudaGetSymbolAddress((void**)&v,    g_v);
    cudaGetSymbolAddress((void**)&q2,   g_q2);
    cudaGetSymbolAddress((void**)&k2,   g_k2);
    cudaGetSymbolAddress((void**)&v2,   g_v2);
    cudaGetSymbolAddress((void**)&cat,  g_cat);
    cudaGetSymbolAddress((void**)&cat2, g_cat2);
    cudaGetSymbolAddress((void**)&O2p,  g_O2p);
    cudaGetSymbolAddress((void**)&l2,   g_l2);

    mod_kernel<<<3 * HID, 256>>>(vec, mw, mb, m);

    // LayerNorms for both blocks up front (block 2 gets its own xm2)
    ln_mod_kernel<<<LX, 384>>>(x, xm, m);
    ln_mod_kernel<<<NC, 384>>>(cps, xm2, m);
    ln_mod_kernel<<<4096, 384>>>(x + (size_t)256 * HID, xm2 + (size_t)NC * HID, m);

    // One merged launch: qkv1 -> h, mlp1(gelu) -> cat[:,HID:], kv2 -> h2kv
    tc_gemm_merged<<<918, 256, SMEM_G2>>>(xm, xm2, w1, h, cat + HID, h2kv, b1);

    // q/k rmsnorm+rope; v via coalesced transpose
    dim3 gqk(LX, NH);
    rmsrope_kernel<<<gqk, HD>>>(h + 0,   QKVW, pe, qs, q, LX, SOFT_SCALE);
    rmsrope_kernel<<<gqk, HD>>>(h + HID, QKVW, pe, ks, k, LX, 1.f);
    transpose_v<<<dim3(LX / 32, 4, NH), dim3(32, 8)>>>(h + 2 * HID, QKVW, v, LX, LX);

    dim3 gk2(L2V, NH);
    rmsrope_kernel<<<gk2, HD>>>(h2kv, 3072, cpe, ks, k2, L2P, 1.f);
    transpose_v<<<dim3((L2V + 31) / 32, 4, NH), dim3(32, 8)>>>(h2kv + HID, 3072, v2, L2P, L2V);

    // block-2 small GEMMs (M=128)
    tc_gemm<256, 4, 0><<<dim3(HID / 256, 1, 1), 256, SM256>>>(
        xm2, w1, h2f, HID, HID, HID, HID, 0, 0, 0, b1, nullptr, 0, nullptr, 128);
    tc_gemm<256, 4, 2><<<dim3(MLP / 256, 1, 1), 256, SM256>>>(
        xm2, w1 + (size_t)QKVW * HID, cat2 + HID, HID, HID, HID, CATW,
        0, 0, 0, b1 + QKVW, nullptr, 0, nullptr, 128);
    rmsrope_kernel<<<dim3(NC, NH), HD>>>(h2f, HID, cpe, qs, q2, 128, SOFT_SCALE);

    // fused attention block 1 -> cat[:,0:HID]
    flash_kernel<0><<<dim3(LX / 128, NH), 256, FL_SMEM>>>(
        q, k, v, cat, nullptr,
        (size_t)LX * HD, (size_t)LX * HD, (size_t)HD * LX, LX,
        LX / 64, LX, CATW);

    // out_x = x + gate * (cat @ w2.T + b2)
    tc_gemm2<1><<<dim3(HID / 256, LX / 256), 256, SMEM_G2>>>(
        cat, w2, out, CATW, CATW, CATW, HID, b2, x, HID, m + 2 * HID, LX);

    // fused attention block 2 (split-K) + combine
    flash_kernel<1><<<dim3(NSPLIT, NH), 256, FL_SMEM>>>(
        q2, k2, v2, O2p, l2,
        (size_t)128 * HD, (size_t)L2P * HD, (size_t)HD * L2P, L2P,
        L2P / 64 / NSPLIT, L2V, 0);
    combine2_kernel<<<dim3(NC, NH), HD>>>(O2p, l2, cat2);

    // concepts_out = concepts + gate * (cat2 @ w2.T + b2)
    tc_gemm<256, 4, 1><<<dim3(HID / 256, 1, 1), 256, SM256>>>(
        cat2, w2, out + (size_t)LX * HID, CATW, CATW, CATW, HID,
        0, 0, 0, b2, cps, HID, m + 2 * HID, NC);
}